// round 1
// baseline (speedup 1.0000x reference)
#include <cuda_runtime.h>
#include <math.h>
#include <stdint.h>

#define TSEQ   2048
#define DMODEL 2048
#define NHEADS 16
#define HDIM   128
#define BATCH  2
#define QKVW   (DMODEL + 2*HDIM)   // 2304

// Scratch (no cudaMalloc allowed)
__device__ float g_qkv[(size_t)BATCH * TSEQ * QKVW];    // 37.7 MB
__device__ float g_attn[(size_t)BATCH * TSEQ * DMODEL]; // 33.5 MB

// ---------------------------------------------------------------------------
// SGEMM: C[M,N] = A[M,K] @ B[K,N], row-major, M%128==0, N%128==0, K%16==0
// 128x128 block tile, BK=16, 256 threads, 8x8 per-thread microtile.
// ---------------------------------------------------------------------------
__global__ __launch_bounds__(256) void sgemm128x128(
    const float* __restrict__ A, const float* __restrict__ B,
    float* __restrict__ C, int M, int N, int K)
{
    __shared__ float As[16][132];   // A transposed: As[k][m], padded
    __shared__ float Bs[16][128];   // Bs[k][n]

    const int tid = threadIdx.x;
    const int tx = tid & 15, ty = tid >> 4;
    const int bm = blockIdx.y * 128, bn = blockIdx.x * 128;

    float acc[8][8];
#pragma unroll
    for (int i = 0; i < 8; i++)
#pragma unroll
        for (int j = 0; j < 8; j++) acc[i][j] = 0.f;

    const float* Ab = A + (size_t)bm * K;
    const float* Bb = B + bn;

    for (int k0 = 0; k0 < K; k0 += 16) {
#pragma unroll
        for (int r = 0; r < 2; r++) {
            int li = r * 256 + tid;
            int row = li >> 2;
            int c4 = (li & 3) * 4;
            float4 v = *(const float4*)(Ab + (size_t)row * K + k0 + c4);
            As[c4 + 0][row] = v.x;
            As[c4 + 1][row] = v.y;
            As[c4 + 2][row] = v.z;
            As[c4 + 3][row] = v.w;
        }
#pragma unroll
        for (int r = 0; r < 2; r++) {
            int li = r * 256 + tid;
            int row = li >> 5;
            int c = (li & 31) * 4;
            *(float4*)&Bs[row][c] = *(const float4*)(Bb + (size_t)(k0 + row) * N + c);
        }
        __syncthreads();
#pragma unroll
        for (int k = 0; k < 16; k++) {
            float a[8], bv[8];
            *(float4*)&a[0]  = *(float4*)&As[k][ty * 8];
            *(float4*)&a[4]  = *(float4*)&As[k][ty * 8 + 4];
            *(float4*)&bv[0] = *(float4*)&Bs[k][tx * 8];
            *(float4*)&bv[4] = *(float4*)&Bs[k][tx * 8 + 4];
#pragma unroll
            for (int i = 0; i < 8; i++)
#pragma unroll
                for (int j = 0; j < 8; j++)
                    acc[i][j] += a[i] * bv[j];
        }
        __syncthreads();
    }

#pragma unroll
    for (int i = 0; i < 8; i++) {
        float* Cr = C + (size_t)(bm + ty * 8 + i) * N + bn + tx * 8;
        *(float4*)Cr       = make_float4(acc[i][0], acc[i][1], acc[i][2], acc[i][3]);
        *(float4*)(Cr + 4) = make_float4(acc[i][4], acc[i][5], acc[i][6], acc[i][7]);
    }
}

// ---------------------------------------------------------------------------
// RoPE in-place on g_qkv: heads 0..15 are q, "head" 16 is k (cols 2048..2175)
// split-half rope: (x1, x2) -> (x1*c - x2*s, x2*c + x1*s)
// ---------------------------------------------------------------------------
__global__ void rope_kernel(float* __restrict__ qkv,
                            const float* __restrict__ sinp,
                            const float* __restrict__ cosp)
{
    int idx = blockIdx.x * 256 + threadIdx.x;
    const int total = BATCH * TSEQ * (NHEADS + 1) * 64;
    if (idx >= total) return;
    int i = idx & 63;
    int rest = idx >> 6;
    int h = rest % (NHEADS + 1);
    int t = (rest / (NHEADS + 1)) % TSEQ;
    int b = rest / ((NHEADS + 1) * TSEQ);
    int col = (h < NHEADS) ? h * HDIM : DMODEL;   // k starts at 2048
    float* base = qkv + ((size_t)(b * TSEQ + t)) * QKVW + col;
    float s = sinp[t * 64 + i];
    float c = cosp[t * 64 + i];
    float x1 = base[i];
    float x2 = base[64 + i];
    base[i]      = x1 * c - x2 * s;
    base[64 + i] = x2 * c + x1 * s;
}

// ---------------------------------------------------------------------------
// Flash attention, fp32, MQA. Tiles 128(q) x 128(kv). Causal + same-doc mask.
// grid = (T/128, NHEADS, BATCH), 256 threads.
// Skips KV tiles strictly before the first token whose doc matches the
// q-tile's first doc id (docs sorted -> sound lower bound).
// ---------------------------------------------------------------------------
#define SMEM_ATTN_FLOATS (128*132*2 + 128*128 + 257)

__global__ __launch_bounds__(256, 1) void attn_kernel(
    const float* __restrict__ qkv, const int* __restrict__ doc,
    float* __restrict__ outa)
{
    extern __shared__ float smf[];
    float* Qt  = smf;                 // [128 d][132] transposed q tile
    float* KV  = Qt + 128 * 132;      // K as Kt[d][132], later V as Vs[n][132]
    float* Ps  = KV + 128 * 132;      // [128 m][128 n] probabilities
    int* docq  = (int*)(Ps + 128 * 128);
    int* dock  = docq + 128;
    int* skst  = dock + 128;

    const int tid = threadIdx.x;
    const int tx = tid & 15, ty = tid >> 4;
    const int qt = blockIdx.x, h = blockIdx.y, b = blockIdx.z;
    const int q0 = qt * 128;
    const float* qbase = qkv + (size_t)b * TSEQ * QKVW;
    const float SCALE = 0.08838834764831845f;  // 1/sqrt(128)

    // load Q tile transposed (rotated store order -> 4-way instead of 16-way conflicts)
#pragma unroll
    for (int r = 0; r < 16; r++) {
        int li = r * 256 + tid;
        int row = li >> 5;
        int lane4 = li & 31;
        int c4 = lane4 * 4;
        float4 v = *(const float4*)(qbase + (size_t)(q0 + row) * QKVW + h * HDIM + c4);
        float vv[4] = {v.x, v.y, v.z, v.w};
#pragma unroll
        for (int u = 0; u < 4; u++) {
            int uu = (u + lane4) & 3;
            Qt[(c4 + uu) * 132 + row] = vv[uu];
        }
    }
    if (tid < 128) docq[tid] = doc[b * TSEQ + q0 + tid];
    if (tid == 0) {
        int d0 = doc[b * TSEQ + q0];
        int lo = 0, hi = q0;
        while (lo < hi) {
            int mid = (lo + hi) >> 1;
            if (doc[b * TSEQ + mid] < d0) lo = mid + 1; else hi = mid;
        }
        skst[0] = lo >> 7;
    }
    __syncthreads();

    const int kt_start = skst[0];

    float m_r[8], l_r[8], o[8][8];
#pragma unroll
    for (int i = 0; i < 8; i++) {
        m_r[i] = -1e30f;
        l_r[i] = 0.f;
#pragma unroll
        for (int j = 0; j < 8; j++) o[i][j] = 0.f;
    }

    int dq[8];
#pragma unroll
    for (int i = 0; i < 8; i++) dq[i] = docq[ty * 8 + i];

    for (int kt = kt_start; kt <= qt; kt++) {
        const int k0 = kt * 128;

        // load K transposed into KV: Kt[d][n]
#pragma unroll
        for (int r = 0; r < 16; r++) {
            int li = r * 256 + tid;
            int row = li >> 5;
            int lane4 = li & 31;
            int c4 = lane4 * 4;
            float4 v = *(const float4*)(qbase + (size_t)(k0 + row) * QKVW + DMODEL + c4);
            float vv[4] = {v.x, v.y, v.z, v.w};
#pragma unroll
            for (int u = 0; u < 4; u++) {
                int uu = (u + lane4) & 3;
                KV[(c4 + uu) * 132 + row] = vv[uu];
            }
        }
        if (tid < 128) dock[tid] = doc[b * TSEQ + k0 + tid];
        __syncthreads();

        // S = Q @ K^T
        float sreg[8][8];
#pragma unroll
        for (int i = 0; i < 8; i++)
#pragma unroll
            for (int j = 0; j < 8; j++) sreg[i][j] = 0.f;

#pragma unroll 2
        for (int d = 0; d < 128; d++) {
            float qa[8], kb[8];
            *(float4*)&qa[0] = *(float4*)&Qt[d * 132 + ty * 8];
            *(float4*)&qa[4] = *(float4*)&Qt[d * 132 + ty * 8 + 4];
            *(float4*)&kb[0] = *(float4*)&KV[d * 132 + tx * 8];
            *(float4*)&kb[4] = *(float4*)&KV[d * 132 + tx * 8 + 4];
#pragma unroll
            for (int i = 0; i < 8; i++)
#pragma unroll
                for (int j = 0; j < 8; j++)
                    sreg[i][j] += qa[i] * kb[j];
        }

        int dk[8];
#pragma unroll
        for (int j = 0; j < 8; j++) dk[j] = dock[tx * 8 + j];

        const int qi0 = q0 + ty * 8, kj0 = k0 + tx * 8;
#pragma unroll
        for (int i = 0; i < 8; i++) {
            const int qi = qi0 + i;
            float mx = -3.0e38f;
#pragma unroll
            for (int j = 0; j < 8; j++) {
                bool ok = (kj0 + j <= qi) && (dk[j] == dq[i]);
                float v = ok ? sreg[i][j] * SCALE : -1.7e38f;
                sreg[i][j] = v;
                mx = fmaxf(mx, v);
            }
#pragma unroll
            for (int off = 8; off; off >>= 1)
                mx = fmaxf(mx, __shfl_xor_sync(0xffffffffu, mx, off, 16));

            float mnew = fmaxf(m_r[i], mx);
            float alpha = __expf(m_r[i] - mnew);
            float sum = 0.f;
#pragma unroll
            for (int j = 0; j < 8; j++) {
                float p = __expf(sreg[i][j] - mnew);
                sreg[i][j] = p;
                sum += p;
            }
#pragma unroll
            for (int off = 8; off; off >>= 1)
                sum += __shfl_xor_sync(0xffffffffu, sum, off, 16);

            l_r[i] = l_r[i] * alpha + sum;
            m_r[i] = mnew;
#pragma unroll
            for (int j = 0; j < 8; j++) o[i][j] *= alpha;

            *(float4*)&Ps[(ty * 8 + i) * 128 + tx * 8] =
                make_float4(sreg[i][0], sreg[i][1], sreg[i][2], sreg[i][3]);
            *(float4*)&Ps[(ty * 8 + i) * 128 + tx * 8 + 4] =
                make_float4(sreg[i][4], sreg[i][5], sreg[i][6], sreg[i][7]);
        }
        __syncthreads();   // Ps visible; K reads done -> safe to overwrite KV

        // load V directly: Vs[n][132]
#pragma unroll
        for (int r = 0; r < 16; r++) {
            int li = r * 256 + tid;
            int row = li >> 5;
            int c4 = (li & 31) * 4;
            float4 v = *(const float4*)(qbase + (size_t)(k0 + row) * QKVW + DMODEL + HDIM + c4);
            *(float4*)&KV[row * 132 + c4] = v;
        }
        __syncthreads();

        // O += P @ V
#pragma unroll 2
        for (int n = 0; n < 128; n++) {
            float vb[8];
            *(float4*)&vb[0] = *(float4*)&KV[n * 132 + tx * 8];
            *(float4*)&vb[4] = *(float4*)&KV[n * 132 + tx * 8 + 4];
            float pa[8];
#pragma unroll
            for (int i = 0; i < 8; i++) pa[i] = Ps[(ty * 8 + i) * 128 + n];
#pragma unroll
            for (int i = 0; i < 8; i++)
#pragma unroll
                for (int j = 0; j < 8; j++)
                    o[i][j] += pa[i] * vb[j];
        }
        __syncthreads();   // done with KV/Ps before next iteration overwrites
    }

    // epilogue: normalize and store (b, t, h*128 + d)
#pragma unroll
    for (int i = 0; i < 8; i++) {
        float inv = 1.0f / l_r[i];
        size_t off = ((size_t)(b * TSEQ + q0 + ty * 8 + i)) * DMODEL + h * HDIM + tx * 8;
        outa[off + 0] = o[i][0] * inv;
        outa[off + 1] = o[i][1] * inv;
        outa[off + 2] = o[i][2] * inv;
        outa[off + 3] = o[i][3] * inv;
        outa[off + 4] = o[i][4] * inv;
        outa[off + 5] = o[i][5] * inv;
        outa[off + 6] = o[i][6] * inv;
        outa[off + 7] = o[i][7] * inv;
    }
}

// ---------------------------------------------------------------------------
extern "C" void kernel_launch(void* const* d_in, const int* in_sizes, int n_in,
                              void* d_out, int out_size)
{
    const float* x    = (const float*)d_in[0];
    const float* sinp = (const float*)d_in[1];
    const float* cosp = (const float*)d_in[2];
    const int*   doc  = (const int*)d_in[3];
    const float* Wqkv = (const float*)d_in[4];
    const float* Wout = (const float*)d_in[5];
    float* out = (float*)d_out;

    float *qkv, *attn;
    cudaGetSymbolAddress((void**)&qkv, g_qkv);
    cudaGetSymbolAddress((void**)&attn, g_attn);

    // 1) qkv = x @ W_qkv
    {
        dim3 g(QKVW / 128, (BATCH * TSEQ) / 128);
        sgemm128x128<<<g, 256>>>(x, Wqkv, qkv, BATCH * TSEQ, QKVW, DMODEL);
    }

    // 2) RoPE on q + k (in place)
    {
        int total = BATCH * TSEQ * (NHEADS + 1) * 64;
        rope_kernel<<<(total + 255) / 256, 256>>>(qkv, sinp, cosp);
    }

    // 3) flash attention
    {
        size_t smem = (size_t)SMEM_ATTN_FLOATS * sizeof(float);
        cudaFuncSetAttribute(attn_kernel, cudaFuncAttributeMaxDynamicSharedMemorySize,
                             (int)smem);
        dim3 g(TSEQ / 128, NHEADS, BATCH);
        attn_kernel<<<g, 256, smem>>>(qkv, doc, attn);
    }

    // 4) out = attn @ W_out
    {
        dim3 g(DMODEL / 128, (BATCH * TSEQ) / 128);
        sgemm128x128<<<g, 256>>>(attn, Wout, out, BATCH * TSEQ, DMODEL, DMODEL);
    }
}

// round 3
// speedup vs baseline: 2.1998x; 2.1998x over previous
#include <cuda_runtime.h>
#include <math.h>
#include <stdint.h>

#define TSEQ   2048
#define DMODEL 2048
#define NHEADS 16
#define HDIM   128
#define BATCH  2
#define QKVW   (DMODEL + 2*HDIM)   // 2304
#define MROWS  (BATCH*TSEQ)        // 4096

// Scratch (no cudaMalloc allowed)
__device__ float g_qkv   [(size_t)BATCH * TSEQ * QKVW];   // 37.7 MB
__device__ float g_attn  [(size_t)BATCH * TSEQ * DMODEL]; // 33.5 MB (tf32-rounded)
__device__ float g_xr    [(size_t)BATCH * TSEQ * DMODEL]; // 33.5 MB (x, tf32-rounded)
__device__ float g_wqkv_t[(size_t)QKVW * DMODEL];         // 18.9 MB (W_qkv^T, tf32)
__device__ float g_wout_t[(size_t)DMODEL * DMODEL];       // 16.8 MB (W_out^T, tf32)

// ---------------------------------------------------------------------------
__device__ __forceinline__ uint32_t smem_u32(const void* p) {
    uint32_t a;
    asm("{ .reg .u64 t; cvta.to.shared.u64 t, %1; cvt.u32.u64 %0, t; }"
        : "=r"(a) : "l"(p));
    return a;
}
__device__ __forceinline__ float to_tf32(float x) {
    uint32_t u;
    asm("cvt.rna.tf32.f32 %0, %1;" : "=r"(u) : "f"(x));
    return __uint_as_float(u);
}
__device__ __forceinline__ void mma_m16n8k8_tf32(float* c, const uint32_t* a,
                                                 uint32_t b0, uint32_t b1) {
    asm volatile(
        "mma.sync.aligned.m16n8k8.row.col.f32.tf32.tf32.f32 "
        "{%0,%1,%2,%3}, {%4,%5,%6,%7}, {%8,%9}, {%0,%1,%2,%3};"
        : "+f"(c[0]), "+f"(c[1]), "+f"(c[2]), "+f"(c[3])
        : "r"(a[0]), "r"(a[1]), "r"(a[2]), "r"(a[3]), "r"(b0), "r"(b1));
}

// ---------------------------------------------------------------------------
// Transpose + tf32-round: Wt[n*K + k] = rna_tf32(W[k*N + n])
// ---------------------------------------------------------------------------
__global__ void transpose_rna(const float* __restrict__ W, float* __restrict__ Wt,
                              int K, int N)
{
    __shared__ float t[32][33];
    int n0 = blockIdx.x * 32, k0 = blockIdx.y * 32;
    int tx = threadIdx.x, ty = threadIdx.y;
#pragma unroll
    for (int r = 0; r < 32; r += 8)
        t[ty + r][tx] = W[(size_t)(k0 + ty + r) * N + n0 + tx];
    __syncthreads();
#pragma unroll
    for (int r = 0; r < 32; r += 8)
        Wt[(size_t)(n0 + ty + r) * K + k0 + tx] = to_tf32(t[tx][ty + r]);
}

// Elementwise tf32 rounding (x -> g_xr), float4 vectorized
__global__ void round_tf32_vec(const float* __restrict__ in, float* __restrict__ out,
                               int n4)
{
    int i = blockIdx.x * 256 + threadIdx.x;
    if (i >= n4) return;
    float4 v = ((const float4*)in)[i];
    v.x = to_tf32(v.x); v.y = to_tf32(v.y); v.z = to_tf32(v.z); v.w = to_tf32(v.w);
    ((float4*)out)[i] = v;
}

// ---------------------------------------------------------------------------
// mma.sync tf32 GEMM: C[M,N] = A[M,K] @ Bt[N,K]^T
// CTA tile 128x128, BK=32, 8 warps (4 M x 2 N), warp tile 32x64.
// A, Bt must be pre-rounded to tf32. 2-stage cp.async pipeline.
// ---------------------------------------------------------------------------
#define BK 32
#define AS_STRIDE 36                          // floats per row (pad 4)
#define TILE_FLOATS (128 * AS_STRIDE)         // 4608 floats = 18432 B
#define GEMM_SMEM (4 * TILE_FLOATS * 4)       // 73728 B (A0,A1,B0,B1)

__global__ __launch_bounds__(256, 2) void gemm_mma_tf32(
    const float* __restrict__ A, const float* __restrict__ Bt,
    float* __restrict__ C, int M, int N, int K)
{
    extern __shared__ float smf[];
    const uint32_t sm0 = smem_u32(smf);

    const int tid  = threadIdx.x;
    const int wid  = tid >> 5, lane = tid & 31;
    const int wm   = wid & 3, wn = wid >> 2;        // warp grid 4 x 2
    const int lr   = lane >> 2, lc = lane & 3;
    const int bm   = blockIdx.y * 128, bn = blockIdx.x * 128;
    const int NC   = K / BK;

    const uint32_t* Au = (const uint32_t*)smf;              // A stages at 0, 4608
    const uint32_t* Bu = (const uint32_t*)(smf + 2 * TILE_FLOATS);

    float acc[2][8][4];
#pragma unroll
    for (int i = 0; i < 2; i++)
#pragma unroll
        for (int j = 0; j < 8; j++)
#pragma unroll
            for (int q = 0; q < 4; q++) acc[i][j][q] = 0.f;

    auto load_stage = [&](int s, int k0) {
        uint32_t sA = sm0 + s * (TILE_FLOATS * 4);
        uint32_t sB = sm0 + (2 + s) * (TILE_FLOATS * 4);
#pragma unroll
        for (int it = 0; it < 4; it++) {
            int idx = it * 256 + tid;
            int row = idx >> 3, c4 = idx & 7;
            const float* g = A + (size_t)(bm + row) * K + k0 + c4 * 4;
            asm volatile("cp.async.cg.shared.global [%0], [%1], 16;"
                         :: "r"(sA + (uint32_t)(row * 144 + c4 * 16)), "l"(g));
        }
#pragma unroll
        for (int it = 0; it < 4; it++) {
            int idx = it * 256 + tid;
            int row = idx >> 3, c4 = idx & 7;
            const float* g = Bt + (size_t)(bn + row) * K + k0 + c4 * 4;
            asm volatile("cp.async.cg.shared.global [%0], [%1], 16;"
                         :: "r"(sB + (uint32_t)(row * 144 + c4 * 16)), "l"(g));
        }
        asm volatile("cp.async.commit_group;" ::: "memory");
    };

    load_stage(0, 0);

    for (int c = 0; c < NC; c++) {
        const int s = c & 1;
        if (c + 1 < NC) {
            load_stage(1 - s, (c + 1) * BK);
            asm volatile("cp.async.wait_group 1;" ::: "memory");
        } else {
            asm volatile("cp.async.wait_group 0;" ::: "memory");
        }
        __syncthreads();

        const uint32_t* As = Au + s * TILE_FLOATS;
        const uint32_t* Bs = Bu + s * TILE_FLOATS;
#pragma unroll
        for (int ks = 0; ks < 4; ks++) {
            const int k0 = ks * 8;
            uint32_t a[2][4];
#pragma unroll
            for (int mt = 0; mt < 2; mt++) {
                int r0 = wm * 32 + mt * 16 + lr;
                a[mt][0] = As[r0 * AS_STRIDE + k0 + lc];
                a[mt][1] = As[(r0 + 8) * AS_STRIDE + k0 + lc];
                a[mt][2] = As[r0 * AS_STRIDE + k0 + 4 + lc];
                a[mt][3] = As[(r0 + 8) * AS_STRIDE + k0 + 4 + lc];
            }
#pragma unroll
            for (int nt = 0; nt < 8; nt++) {
                int nr = wn * 64 + nt * 8 + lr;
                uint32_t b0 = Bs[nr * AS_STRIDE + k0 + lc];
                uint32_t b1 = Bs[nr * AS_STRIDE + k0 + 4 + lc];
                mma_m16n8k8_tf32(acc[0][nt], a[0], b0, b1);
                mma_m16n8k8_tf32(acc[1][nt], a[1], b0, b1);
            }
        }
        __syncthreads();
    }

    // epilogue
#pragma unroll
    for (int mt = 0; mt < 2; mt++) {
        int row = bm + wm * 32 + mt * 16 + lr;
#pragma unroll
        for (int nt = 0; nt < 8; nt++) {
            int col = bn + wn * 64 + nt * 8 + lc * 2;
            *(float2*)(C + (size_t)row * N + col) =
                make_float2(acc[mt][nt][0], acc[mt][nt][1]);
            *(float2*)(C + (size_t)(row + 8) * N + col) =
                make_float2(acc[mt][nt][2], acc[mt][nt][3]);
        }
    }
}

// ---------------------------------------------------------------------------
// RoPE in-place on g_qkv
// ---------------------------------------------------------------------------
__global__ void rope_kernel(float* __restrict__ qkv,
                            const float* __restrict__ sinp,
                            const float* __restrict__ cosp)
{
    int idx = blockIdx.x * 256 + threadIdx.x;
    const int total = BATCH * TSEQ * (NHEADS + 1) * 64;
    if (idx >= total) return;
    int i = idx & 63;
    int rest = idx >> 6;
    int h = rest % (NHEADS + 1);
    int t = (rest / (NHEADS + 1)) % TSEQ;
    int b = rest / ((NHEADS + 1) * TSEQ);
    int col = (h < NHEADS) ? h * HDIM : DMODEL;
    float* base = qkv + ((size_t)(b * TSEQ + t)) * QKVW + col;
    float s = sinp[t * 64 + i];
    float c = cosp[t * 64 + i];
    float x1 = base[i];
    float x2 = base[64 + i];
    base[i]      = x1 * c - x2 * s;
    base[64 + i] = x2 * c + x1 * s;
}

// ---------------------------------------------------------------------------
// Flash attention (fp32). Output rounded to tf32 for the W_out GEMM.
// ---------------------------------------------------------------------------
#define SMEM_ATTN_FLOATS (128*132*2 + 128*128 + 257)

__global__ __launch_bounds__(256, 1) void attn_kernel(
    const float* __restrict__ qkv, const int* __restrict__ doc,
    float* __restrict__ outa)
{
    extern __shared__ float smf[];
    float* Qt  = smf;
    float* KV  = Qt + 128 * 132;
    float* Ps  = KV + 128 * 132;
    int* docq  = (int*)(Ps + 128 * 128);
    int* dock  = docq + 128;
    int* skst  = dock + 128;

    const int tid = threadIdx.x;
    const int tx = tid & 15, ty = tid >> 4;
    const int qt = blockIdx.x, h = blockIdx.y, b = blockIdx.z;
    const int q0 = qt * 128;
    const float* qbase = qkv + (size_t)b * TSEQ * QKVW;
    const float SCALE = 0.08838834764831845f;

#pragma unroll
    for (int r = 0; r < 16; r++) {
        int li = r * 256 + tid;
        int row = li >> 5;
        int lane4 = li & 31;
        int c4 = lane4 * 4;
        float4 v = *(const float4*)(qbase + (size_t)(q0 + row) * QKVW + h * HDIM + c4);
        float vv[4] = {v.x, v.y, v.z, v.w};
#pragma unroll
        for (int u = 0; u < 4; u++) {
            int uu = (u + lane4) & 3;
            Qt[(c4 + uu) * 132 + row] = vv[uu];
        }
    }
    if (tid < 128) docq[tid] = doc[b * TSEQ + q0 + tid];
    if (tid == 0) {
        int d0 = doc[b * TSEQ + q0];
        int lo = 0, hi = q0;
        while (lo < hi) {
            int mid = (lo + hi) >> 1;
            if (doc[b * TSEQ + mid] < d0) lo = mid + 1; else hi = mid;
        }
        skst[0] = lo >> 7;
    }
    __syncthreads();

    const int kt_start = skst[0];

    float m_r[8], l_r[8], o[8][8];
#pragma unroll
    for (int i = 0; i < 8; i++) {
        m_r[i] = -1e30f;
        l_r[i] = 0.f;
#pragma unroll
        for (int j = 0; j < 8; j++) o[i][j] = 0.f;
    }

    int dq[8];
#pragma unroll
    for (int i = 0; i < 8; i++) dq[i] = docq[ty * 8 + i];

    for (int kt = kt_start; kt <= qt; kt++) {
        const int k0 = kt * 128;

#pragma unroll
        for (int r = 0; r < 16; r++) {
            int li = r * 256 + tid;
            int row = li >> 5;
            int lane4 = li & 31;
            int c4 = lane4 * 4;
            float4 v = *(const float4*)(qbase + (size_t)(k0 + row) * QKVW + DMODEL + c4);
            float vv[4] = {v.x, v.y, v.z, v.w};
#pragma unroll
            for (int u = 0; u < 4; u++) {
                int uu = (u + lane4) & 3;
                KV[(c4 + uu) * 132 + row] = vv[uu];
            }
        }
        if (tid < 128) dock[tid] = doc[b * TSEQ + k0 + tid];
        __syncthreads();

        float sreg[8][8];
#pragma unroll
        for (int i = 0; i < 8; i++)
#pragma unroll
            for (int j = 0; j < 8; j++) sreg[i][j] = 0.f;

#pragma unroll 2
        for (int d = 0; d < 128; d++) {
            float qa[8], kb[8];
            *(float4*)&qa[0] = *(float4*)&Qt[d * 132 + ty * 8];
            *(float4*)&qa[4] = *(float4*)&Qt[d * 132 + ty * 8 + 4];
            *(float4*)&kb[0] = *(float4*)&KV[d * 132 + tx * 8];
            *(float4*)&kb[4] = *(float4*)&KV[d * 132 + tx * 8 + 4];
#pragma unroll
            for (int i = 0; i < 8; i++)
#pragma unroll
                for (int j = 0; j < 8; j++)
                    sreg[i][j] += qa[i] * kb[j];
        }

        int dk[8];
#pragma unroll
        for (int j = 0; j < 8; j++) dk[j] = dock[tx * 8 + j];

        const int qi0 = q0 + ty * 8, kj0 = k0 + tx * 8;
#pragma unroll
        for (int i = 0; i < 8; i++) {
            const int qi = qi0 + i;
            float mx = -3.0e38f;
#pragma unroll
            for (int j = 0; j < 8; j++) {
                bool ok = (kj0 + j <= qi) && (dk[j] == dq[i]);
                float v = ok ? sreg[i][j] * SCALE : -1.7e38f;
                sreg[i][j] = v;
                mx = fmaxf(mx, v);
            }
#pragma unroll
            for (int off = 8; off; off >>= 1)
                mx = fmaxf(mx, __shfl_xor_sync(0xffffffffu, mx, off, 16));

            float mnew = fmaxf(m_r[i], mx);
            float alpha = __expf(m_r[i] - mnew);
            float sum = 0.f;
#pragma unroll
            for (int j = 0; j < 8; j++) {
                float p = __expf(sreg[i][j] - mnew);
                sreg[i][j] = p;
                sum += p;
            }
#pragma unroll
            for (int off = 8; off; off >>= 1)
                sum += __shfl_xor_sync(0xffffffffu, sum, off, 16);

            l_r[i] = l_r[i] * alpha + sum;
            m_r[i] = mnew;
#pragma unroll
            for (int j = 0; j < 8; j++) o[i][j] *= alpha;

            *(float4*)&Ps[(ty * 8 + i) * 128 + tx * 8] =
                make_float4(sreg[i][0], sreg[i][1], sreg[i][2], sreg[i][3]);
            *(float4*)&Ps[(ty * 8 + i) * 128 + tx * 8 + 4] =
                make_float4(sreg[i][4], sreg[i][5], sreg[i][6], sreg[i][7]);
        }
        __syncthreads();

#pragma unroll
        for (int r = 0; r < 16; r++) {
            int li = r * 256 + tid;
            int row = li >> 5;
            int c4 = (li & 31) * 4;
            float4 v = *(const float4*)(qbase + (size_t)(k0 + row) * QKVW + DMODEL + HDIM + c4);
            *(float4*)&KV[row * 132 + c4] = v;
        }
        __syncthreads();

#pragma unroll 2
        for (int n = 0; n < 128; n++) {
            float vb[8];
            *(float4*)&vb[0] = *(float4*)&KV[n * 132 + tx * 8];
            *(float4*)&vb[4] = *(float4*)&KV[n * 132 + tx * 8 + 4];
            float pa[8];
#pragma unroll
            for (int i = 0; i < 8; i++) pa[i] = Ps[(ty * 8 + i) * 128 + n];
#pragma unroll
            for (int i = 0; i < 8; i++)
#pragma unroll
                for (int j = 0; j < 8; j++)
                    o[i][j] += pa[i] * vb[j];
        }
        __syncthreads();
    }

#pragma unroll
    for (int i = 0; i < 8; i++) {
        float inv = 1.0f / l_r[i];
        size_t off = ((size_t)(b * TSEQ + q0 + ty * 8 + i)) * DMODEL + h * HDIM + tx * 8;
#pragma unroll
        for (int j = 0; j < 8; j++)
            outa[off + j] = to_tf32(o[i][j] * inv);
    }
}

// ---------------------------------------------------------------------------
extern "C" void kernel_launch(void* const* d_in, const int* in_sizes, int n_in,
                              void* d_out, int out_size)
{
    const float* x    = (const float*)d_in[0];
    const float* sinp = (const float*)d_in[1];
    const float* cosp = (const float*)d_in[2];
    const int*   doc  = (const int*)d_in[3];
    const float* Wqkv = (const float*)d_in[4];
    const float* Wout = (const float*)d_in[5];
    float* out = (float*)d_out;

    float *qkv, *attn, *xr, *wqkv_t, *wout_t;
    cudaGetSymbolAddress((void**)&qkv,    g_qkv);
    cudaGetSymbolAddress((void**)&attn,   g_attn);
    cudaGetSymbolAddress((void**)&xr,     g_xr);
    cudaGetSymbolAddress((void**)&wqkv_t, g_wqkv_t);
    cudaGetSymbolAddress((void**)&wout_t, g_wout_t);

    cudaFuncSetAttribute(gemm_mma_tf32, cudaFuncAttributeMaxDynamicSharedMemorySize,
                         GEMM_SMEM);

    // 0) weight transposes (+rna round) and x rounding
    {
        dim3 b(32, 8);
        transpose_rna<<<dim3(QKVW / 32, DMODEL / 32), b>>>(Wqkv, wqkv_t, DMODEL, QKVW);
        transpose_rna<<<dim3(DMODEL / 32, DMODEL / 32), b>>>(Wout, wout_t, DMODEL, DMODEL);
        int n4 = MROWS * DMODEL / 4;
        round_tf32_vec<<<(n4 + 255) / 256, 256>>>(x, xr, n4);
    }

    // 1) qkv = x @ W_qkv  (tensor cores, tf32)
    {
        dim3 g(QKVW / 128, MROWS / 128);
        gemm_mma_tf32<<<g, 256, GEMM_SMEM>>>(xr, wqkv_t, qkv, MROWS, QKVW, DMODEL);
    }

    // 2) RoPE
    {
        int total = BATCH * TSEQ * (NHEADS + 1) * 64;
        rope_kernel<<<(total + 255) / 256, 256>>>(qkv, sinp, cosp);
    }

    // 3) flash attention (outputs tf32-rounded)
    {
        size_t smem = (size_t)SMEM_ATTN_FLOATS * sizeof(float);
        cudaFuncSetAttribute(attn_kernel, cudaFuncAttributeMaxDynamicSharedMemorySize,
                             (int)smem);
        dim3 g(TSEQ / 128, NHEADS, BATCH);
        attn_kernel<<<g, 256, smem>>>(qkv, doc, attn);
    }

    // 4) out = attn @ W_out  (tensor cores, tf32)
    {
        dim3 g(DMODEL / 128, MROWS / 128);
        gemm_mma_tf32<<<g, 256, GEMM_SMEM>>>(attn, wout_t, out, MROWS, DMODEL, DMODEL);
    }
}

// round 4
// speedup vs baseline: 3.0012x; 1.3643x over previous
#include <cuda_runtime.h>
#include <math.h>
#include <stdint.h>

#define TSEQ   2048
#define DMODEL 2048
#define NHEADS 16
#define HDIM   128
#define BATCH  2
#define QKVW   (DMODEL + 2*HDIM)   // 2304
#define MROWS  (BATCH*TSEQ)        // 4096

__device__ float g_qkv   [(size_t)BATCH * TSEQ * QKVW];
__device__ float g_attn  [(size_t)BATCH * TSEQ * DMODEL];
__device__ float g_xr    [(size_t)BATCH * TSEQ * DMODEL];
__device__ float g_wqkv_t[(size_t)QKVW * DMODEL];
__device__ float g_wout_t[(size_t)DMODEL * DMODEL];

// ---------------------------------------------------------------------------
__device__ __forceinline__ uint32_t smem_u32(const void* p) {
    uint32_t a;
    asm("{ .reg .u64 t; cvta.to.shared.u64 t, %1; cvt.u32.u64 %0, t; }"
        : "=r"(a) : "l"(p));
    return a;
}
__device__ __forceinline__ float to_tf32(float x) {
    uint32_t u;
    asm("cvt.rna.tf32.f32 %0, %1;" : "=r"(u) : "f"(x));
    return __uint_as_float(u);
}
__device__ __forceinline__ void mma_m16n8k8_tf32(float* c, const uint32_t* a,
                                                 uint32_t b0, uint32_t b1) {
    asm volatile(
        "mma.sync.aligned.m16n8k8.row.col.f32.tf32.tf32.f32 "
        "{%0,%1,%2,%3}, {%4,%5,%6,%7}, {%8,%9}, {%0,%1,%2,%3};"
        : "+f"(c[0]), "+f"(c[1]), "+f"(c[2]), "+f"(c[3])
        : "r"(a[0]), "r"(a[1]), "r"(a[2]), "r"(a[3]), "r"(b0), "r"(b1));
}

// ---------------------------------------------------------------------------
__global__ void transpose_rna(const float* __restrict__ W, float* __restrict__ Wt,
                              int K, int N)
{
    __shared__ float t[32][33];
    int n0 = blockIdx.x * 32, k0 = blockIdx.y * 32;
    int tx = threadIdx.x, ty = threadIdx.y;
#pragma unroll
    for (int r = 0; r < 32; r += 8)
        t[ty + r][tx] = W[(size_t)(k0 + ty + r) * N + n0 + tx];
    __syncthreads();
#pragma unroll
    for (int r = 0; r < 32; r += 8)
        Wt[(size_t)(n0 + ty + r) * K + k0 + tx] = to_tf32(t[tx][ty + r]);
}

__global__ void round_tf32_vec(const float* __restrict__ in, float* __restrict__ out,
                               int n4)
{
    int i = blockIdx.x * 256 + threadIdx.x;
    if (i >= n4) return;
    float4 v = ((const float4*)in)[i];
    v.x = to_tf32(v.x); v.y = to_tf32(v.y); v.z = to_tf32(v.z); v.w = to_tf32(v.w);
    ((float4*)out)[i] = v;
}

// ---------------------------------------------------------------------------
// mma.sync tf32 GEMM: C[M,N] = A[M,K] @ Bt[N,K]^T. 128x128 tile, BK=32,
// 8 warps (4x2), 3-stage cp.async pipeline.
// ---------------------------------------------------------------------------
#define BK 32
#define AS_STRIDE 36
#define TILE_FLOATS (128 * AS_STRIDE)          // 4608
#define GEMM_SMEM (6 * TILE_FLOATS * 4)        // 110592 B (A0..A2, B0..B2)

__global__ __launch_bounds__(256, 2) void gemm_mma_tf32(
    const float* __restrict__ A, const float* __restrict__ Bt,
    float* __restrict__ C, int M, int N, int K)
{
    extern __shared__ float smf[];
    const uint32_t sm0 = smem_u32(smf);

    const int tid  = threadIdx.x;
    const int wid  = tid >> 5, lane = tid & 31;
    const int wm   = wid & 3, wn = wid >> 2;
    const int lr   = lane >> 2, lc = lane & 3;
    const int bm   = blockIdx.y * 128, bn = blockIdx.x * 128;
    const int NC   = K / BK;

    const uint32_t* Au = (const uint32_t*)smf;
    const uint32_t* Bu = (const uint32_t*)(smf + 3 * TILE_FLOATS);

    float acc[2][8][4];
#pragma unroll
    for (int i = 0; i < 2; i++)
#pragma unroll
        for (int j = 0; j < 8; j++)
#pragma unroll
            for (int q = 0; q < 4; q++) acc[i][j][q] = 0.f;

    auto load_stage = [&](int s, int k0) {
        uint32_t sA = sm0 + s * (TILE_FLOATS * 4);
        uint32_t sB = sm0 + (3 + s) * (TILE_FLOATS * 4);
#pragma unroll
        for (int it = 0; it < 4; it++) {
            int idx = it * 256 + tid;
            int row = idx >> 3, c4 = idx & 7;
            const float* g = A + (size_t)(bm + row) * K + k0 + c4 * 4;
            asm volatile("cp.async.cg.shared.global [%0], [%1], 16;"
                         :: "r"(sA + (uint32_t)(row * 144 + c4 * 16)), "l"(g));
        }
#pragma unroll
        for (int it = 0; it < 4; it++) {
            int idx = it * 256 + tid;
            int row = idx >> 3, c4 = idx & 7;
            const float* g = Bt + (size_t)(bn + row) * K + k0 + c4 * 4;
            asm volatile("cp.async.cg.shared.global [%0], [%1], 16;"
                         :: "r"(sB + (uint32_t)(row * 144 + c4 * 16)), "l"(g));
        }
        asm volatile("cp.async.commit_group;" ::: "memory");
    };

    load_stage(0, 0);
    load_stage(1, BK);

    int s = 0;
    for (int c = 0; c < NC; c++) {
        int s2 = s + 2; if (s2 >= 3) s2 -= 3;
        if (c + 2 < NC) {
            load_stage(s2, (c + 2) * BK);
            asm volatile("cp.async.wait_group 2;" ::: "memory");
        } else if (c + 1 < NC) {
            asm volatile("cp.async.wait_group 1;" ::: "memory");
        } else {
            asm volatile("cp.async.wait_group 0;" ::: "memory");
        }
        __syncthreads();

        const uint32_t* As = Au + s * TILE_FLOATS;
        const uint32_t* Bs = Bu + s * TILE_FLOATS;
#pragma unroll
        for (int ks = 0; ks < 4; ks++) {
            const int k0 = ks * 8;
            uint32_t a[2][4];
#pragma unroll
            for (int mt = 0; mt < 2; mt++) {
                int r0 = wm * 32 + mt * 16 + lr;
                a[mt][0] = As[r0 * AS_STRIDE + k0 + lc];
                a[mt][1] = As[(r0 + 8) * AS_STRIDE + k0 + lc];
                a[mt][2] = As[r0 * AS_STRIDE + k0 + 4 + lc];
                a[mt][3] = As[(r0 + 8) * AS_STRIDE + k0 + 4 + lc];
            }
#pragma unroll
            for (int nt = 0; nt < 8; nt++) {
                int nr = wn * 64 + nt * 8 + lr;
                uint32_t b0 = Bs[nr * AS_STRIDE + k0 + lc];
                uint32_t b1 = Bs[nr * AS_STRIDE + k0 + 4 + lc];
                mma_m16n8k8_tf32(acc[0][nt], a[0], b0, b1);
                mma_m16n8k8_tf32(acc[1][nt], a[1], b0, b1);
            }
        }
        __syncthreads();
        s++; if (s == 3) s = 0;
    }

#pragma unroll
    for (int mt = 0; mt < 2; mt++) {
        int row = bm + wm * 32 + mt * 16 + lr;
#pragma unroll
        for (int nt = 0; nt < 8; nt++) {
            int col = bn + wn * 64 + nt * 8 + lc * 2;
            *(float2*)(C + (size_t)row * N + col) =
                make_float2(acc[mt][nt][0], acc[mt][nt][1]);
            *(float2*)(C + (size_t)(row + 8) * N + col) =
                make_float2(acc[mt][nt][2], acc[mt][nt][3]);
        }
    }
}

// ---------------------------------------------------------------------------
__global__ void rope_kernel(float* __restrict__ qkv,
                            const float* __restrict__ sinp,
                            const float* __restrict__ cosp)
{
    int idx = blockIdx.x * 256 + threadIdx.x;
    const int total = BATCH * TSEQ * (NHEADS + 1) * 64;
    if (idx >= total) return;
    int i = idx & 63;
    int rest = idx >> 6;
    int h = rest % (NHEADS + 1);
    int t = (rest / (NHEADS + 1)) % TSEQ;
    int b = rest / ((NHEADS + 1) * TSEQ);
    int col = (h < NHEADS) ? h * HDIM : DMODEL;
    float* base = qkv + ((size_t)(b * TSEQ + t)) * QKVW + col;
    float s = sinp[t * 64 + i];
    float c = cosp[t * 64 + i];
    float x1 = base[i];
    float x2 = base[64 + i];
    base[i]      = x1 * c - x2 * s;
    base[64 + i] = x2 * c + x1 * s;
}

// ---------------------------------------------------------------------------
// Flash attention via mma.sync tf32.
// 8 warps; warp w owns q-rows [w*16, w*16+16) x all 128 kv cols.
// Smem: Qs[128][132] (tf32), KVs[128][132] (K then V^T, tf32), Ps[128][132].
// ---------------------------------------------------------------------------
#define AST 132
#define ATT_SMEM_BYTES ((3 * 128 * AST + 260) * 4)

__global__ __launch_bounds__(256, 1) void attn_mma(
    const float* __restrict__ qkv, const int* __restrict__ doc,
    float* __restrict__ outa)
{
    extern __shared__ float smf[];
    float* Qs = smf;                       // [128][132]
    float* KVs = Qs + 128 * AST;           // K: [token][d]; later V^T: [d][token]
    float* Ps  = KVs + 128 * AST;          // [128][132]
    int* docq  = (int*)(Ps + 128 * AST);
    int* dock  = docq + 128;
    int* skst  = dock + 128;

    const uint32_t* Qu = (const uint32_t*)Qs;
    const uint32_t* Ku = (const uint32_t*)KVs;
    const uint32_t* Pu = (const uint32_t*)Ps;

    const int tid = threadIdx.x;
    const int wid = tid >> 5, lane = tid & 31;
    const int lr = lane >> 2, lc = lane & 3;
    const int qt = blockIdx.x, h = blockIdx.y, b = blockIdx.z;
    const int q0 = qt * 128;
    const float* qbase = qkv + (size_t)b * TSEQ * QKVW;
    const float SCALE = 0.08838834764831845f;

    // load Q tile, rounded, row-major
#pragma unroll
    for (int r = 0; r < 16; r++) {
        int li = r * 256 + tid;
        int row = li >> 5;
        int c4 = (li & 31) * 4;
        float4 v = *(const float4*)(qbase + (size_t)(q0 + row) * QKVW + h * HDIM + c4);
        v.x = to_tf32(v.x); v.y = to_tf32(v.y); v.z = to_tf32(v.z); v.w = to_tf32(v.w);
        *(float4*)&Qs[row * AST + c4] = v;
    }
    if (tid < 128) docq[tid] = doc[b * TSEQ + q0 + tid];
    if (tid == 0) {
        int d0 = doc[b * TSEQ + q0];
        int lo = 0, hi = q0;
        while (lo < hi) {
            int mid = (lo + hi) >> 1;
            if (doc[b * TSEQ + mid] < d0) lo = mid + 1; else hi = mid;
        }
        skst[0] = lo >> 7;
    }
    __syncthreads();

    const int kt_start = skst[0];
    const int r0g = q0 + wid * 16 + lr;      // global row of "low" accum rows
    const int r1g = r0g + 8;
    const int dq0 = docq[wid * 16 + lr];
    const int dq1 = docq[wid * 16 + lr + 8];

    float m0 = -1e30f, m1 = -1e30f, l0 = 0.f, l1 = 0.f;
    float O[16][4];
#pragma unroll
    for (int nt = 0; nt < 16; nt++)
#pragma unroll
        for (int q = 0; q < 4; q++) O[nt][q] = 0.f;

    for (int kt = kt_start; kt <= qt; kt++) {
        const int k0tok = kt * 128;
        const bool diag = (kt == qt);

        // load K tile [token][d], rounded
#pragma unroll
        for (int r = 0; r < 16; r++) {
            int li = r * 256 + tid;
            int row = li >> 5;
            int c4 = (li & 31) * 4;
            float4 v = *(const float4*)(qbase + (size_t)(k0tok + row) * QKVW + DMODEL + c4);
            v.x = to_tf32(v.x); v.y = to_tf32(v.y); v.z = to_tf32(v.z); v.w = to_tf32(v.w);
            *(float4*)&KVs[row * AST + c4] = v;
        }
        if (tid < 128) dock[tid] = doc[b * TSEQ + k0tok + tid];
        __syncthreads();

        // S = Q @ K^T
        float S[16][4];
#pragma unroll
        for (int nt = 0; nt < 16; nt++)
#pragma unroll
            for (int q = 0; q < 4; q++) S[nt][q] = 0.f;

#pragma unroll 2
        for (int k8 = 0; k8 < 16; k8++) {
            const int kk = k8 * 8;
            uint32_t a[4];
            a[0] = Qu[(wid * 16 + lr) * AST + kk + lc];
            a[1] = Qu[(wid * 16 + lr + 8) * AST + kk + lc];
            a[2] = Qu[(wid * 16 + lr) * AST + kk + 4 + lc];
            a[3] = Qu[(wid * 16 + lr + 8) * AST + kk + 4 + lc];
#pragma unroll
            for (int nt = 0; nt < 16; nt++) {
                uint32_t b0 = Ku[(nt * 8 + lr) * AST + kk + lc];
                uint32_t b1 = Ku[(nt * 8 + lr) * AST + kk + 4 + lc];
                mma_m16n8k8_tf32(S[nt], a, b0, b1);
            }
        }

        // mask + online softmax
        float mx0 = -3.0e38f, mx1 = -3.0e38f;
#pragma unroll
        for (int nt = 0; nt < 16; nt++) {
            int cl = nt * 8 + 2 * lc;
            int2 dk = *(const int2*)&dock[cl];
            int gc0 = k0tok + cl, gc1 = gc0 + 1;
            bool ok00 = (dk.x == dq0) && (!diag || gc0 <= r0g);
            bool ok01 = (dk.y == dq0) && (!diag || gc1 <= r0g);
            bool ok10 = (dk.x == dq1) && (!diag || gc0 <= r1g);
            bool ok11 = (dk.y == dq1) && (!diag || gc1 <= r1g);
            S[nt][0] = ok00 ? S[nt][0] * SCALE : -1.7e38f;
            S[nt][1] = ok01 ? S[nt][1] * SCALE : -1.7e38f;
            S[nt][2] = ok10 ? S[nt][2] * SCALE : -1.7e38f;
            S[nt][3] = ok11 ? S[nt][3] * SCALE : -1.7e38f;
            mx0 = fmaxf(mx0, fmaxf(S[nt][0], S[nt][1]));
            mx1 = fmaxf(mx1, fmaxf(S[nt][2], S[nt][3]));
        }
        mx0 = fmaxf(mx0, __shfl_xor_sync(0xffffffffu, mx0, 1));
        mx0 = fmaxf(mx0, __shfl_xor_sync(0xffffffffu, mx0, 2));
        mx1 = fmaxf(mx1, __shfl_xor_sync(0xffffffffu, mx1, 1));
        mx1 = fmaxf(mx1, __shfl_xor_sync(0xffffffffu, mx1, 2));

        float mn0 = fmaxf(m0, mx0), mn1 = fmaxf(m1, mx1);
        float al0 = __expf(m0 - mn0), al1 = __expf(m1 - mn1);
        float sum0 = 0.f, sum1 = 0.f;
#pragma unroll
        for (int nt = 0; nt < 16; nt++) {
            float p00 = __expf(S[nt][0] - mn0);
            float p01 = __expf(S[nt][1] - mn0);
            float p10 = __expf(S[nt][2] - mn1);
            float p11 = __expf(S[nt][3] - mn1);
            sum0 += p00 + p01;
            sum1 += p10 + p11;
            int cl = nt * 8 + 2 * lc;
            *(float2*)&Ps[(wid * 16 + lr) * AST + cl] =
                make_float2(to_tf32(p00), to_tf32(p01));
            *(float2*)&Ps[(wid * 16 + lr + 8) * AST + cl] =
                make_float2(to_tf32(p10), to_tf32(p11));
        }
        sum0 += __shfl_xor_sync(0xffffffffu, sum0, 1);
        sum0 += __shfl_xor_sync(0xffffffffu, sum0, 2);
        sum1 += __shfl_xor_sync(0xffffffffu, sum1, 1);
        sum1 += __shfl_xor_sync(0xffffffffu, sum1, 2);
        l0 = l0 * al0 + sum0; m0 = mn0;
        l1 = l1 * al1 + sum1; m1 = mn1;
#pragma unroll
        for (int nt = 0; nt < 16; nt++) {
            O[nt][0] *= al0; O[nt][1] *= al0;
            O[nt][2] *= al1; O[nt][3] *= al1;
        }
        __syncthreads();   // all warps done reading K; Ps written

        // load V^T into KVs: Vt[d][token], rounded, rotated stores
#pragma unroll
        for (int r = 0; r < 16; r++) {
            int li = r * 256 + tid;
            int row = li >> 5;
            int lane4 = li & 31;
            int c4 = lane4 * 4;
            float4 v = *(const float4*)(qbase + (size_t)(k0tok + row) * QKVW + DMODEL + HDIM + c4);
            float vv[4] = {to_tf32(v.x), to_tf32(v.y), to_tf32(v.z), to_tf32(v.w)};
#pragma unroll
            for (int u = 0; u < 4; u++) {
                int uu = (u + lane4) & 3;
                KVs[(c4 + uu) * AST + row] = vv[uu];
            }
        }
        __syncthreads();

        // O += P @ V   (A = Ps rows, B = Vt[d][token])
#pragma unroll 2
        for (int k8 = 0; k8 < 16; k8++) {
            const int kk = k8 * 8;
            uint32_t a[4];
            a[0] = Pu[(wid * 16 + lr) * AST + kk + lc];
            a[1] = Pu[(wid * 16 + lr + 8) * AST + kk + lc];
            a[2] = Pu[(wid * 16 + lr) * AST + kk + 4 + lc];
            a[3] = Pu[(wid * 16 + lr + 8) * AST + kk + 4 + lc];
#pragma unroll
            for (int nt = 0; nt < 16; nt++) {
                uint32_t b0 = Ku[(nt * 8 + lr) * AST + kk + lc];
                uint32_t b1 = Ku[(nt * 8 + lr) * AST + kk + 4 + lc];
                mma_m16n8k8_tf32(O[nt], a, b0, b1);
            }
        }
        __syncthreads();   // before next K load overwrites KVs
    }

    // epilogue: normalize, tf32-round, store
    float inv0 = 1.0f / l0, inv1 = 1.0f / l1;
    float* out0 = outa + (size_t)(b * TSEQ + r0g) * DMODEL + h * HDIM;
    float* out1 = outa + (size_t)(b * TSEQ + r1g) * DMODEL + h * HDIM;
#pragma unroll
    for (int nt = 0; nt < 16; nt++) {
        int cl = nt * 8 + 2 * lc;
        *(float2*)(out0 + cl) = make_float2(to_tf32(O[nt][0] * inv0),
                                            to_tf32(O[nt][1] * inv0));
        *(float2*)(out1 + cl) = make_float2(to_tf32(O[nt][2] * inv1),
                                            to_tf32(O[nt][3] * inv1));
    }
}

// ---------------------------------------------------------------------------
extern "C" void kernel_launch(void* const* d_in, const int* in_sizes, int n_in,
                              void* d_out, int out_size)
{
    const float* x    = (const float*)d_in[0];
    const float* sinp = (const float*)d_in[1];
    const float* cosp = (const float*)d_in[2];
    const int*   doc  = (const int*)d_in[3];
    const float* Wqkv = (const float*)d_in[4];
    const float* Wout = (const float*)d_in[5];
    float* out = (float*)d_out;

    float *qkv, *attn, *xr, *wqkv_t, *wout_t;
    cudaGetSymbolAddress((void**)&qkv,    g_qkv);
    cudaGetSymbolAddress((void**)&attn,   g_attn);
    cudaGetSymbolAddress((void**)&xr,     g_xr);
    cudaGetSymbolAddress((void**)&wqkv_t, g_wqkv_t);
    cudaGetSymbolAddress((void**)&wout_t, g_wout_t);

    cudaFuncSetAttribute(gemm_mma_tf32, cudaFuncAttributeMaxDynamicSharedMemorySize,
                         GEMM_SMEM);
    cudaFuncSetAttribute(attn_mma, cudaFuncAttributeMaxDynamicSharedMemorySize,
                         ATT_SMEM_BYTES);

    // 0) prep: weight transposes (+rna) and x rounding
    {
        dim3 bdim(32, 8);
        transpose_rna<<<dim3(QKVW / 32, DMODEL / 32), bdim>>>(Wqkv, wqkv_t, DMODEL, QKVW);
        transpose_rna<<<dim3(DMODEL / 32, DMODEL / 32), bdim>>>(Wout, wout_t, DMODEL, DMODEL);
        int n4 = MROWS * DMODEL / 4;
        round_tf32_vec<<<(n4 + 255) / 256, 256>>>(x, xr, n4);
    }

    // 1) qkv = x @ W_qkv
    {
        dim3 g(QKVW / 128, MROWS / 128);
        gemm_mma_tf32<<<g, 256, GEMM_SMEM>>>(xr, wqkv_t, qkv, MROWS, QKVW, DMODEL);
    }

    // 2) RoPE
    {
        int total = BATCH * TSEQ * (NHEADS + 1) * 64;
        rope_kernel<<<(total + 255) / 256, 256>>>(qkv, sinp, cosp);
    }

    // 3) flash attention (tensor cores)
    {
        dim3 g(TSEQ / 128, NHEADS, BATCH);
        attn_mma<<<g, 256, ATT_SMEM_BYTES>>>(qkv, doc, attn);
    }

    // 4) out = attn @ W_out
    {
        dim3 g(DMODEL / 128, MROWS / 128);
        gemm_mma_tf32<<<g, 256, GEMM_SMEM>>>(attn, wout_t, out, MROWS, DMODEL, DMODEL);
    }
}

// round 5
// speedup vs baseline: 3.2924x; 1.0970x over previous
#include <cuda_runtime.h>
#include <math.h>
#include <stdint.h>

#define TSEQ   2048
#define DMODEL 2048
#define NHEADS 16
#define HDIM   128
#define BATCH  2
#define QKVW   (DMODEL + 2*HDIM)   // 2304
#define MROWS  (BATCH*TSEQ)        // 4096

__device__ float g_qkv   [(size_t)BATCH * TSEQ * QKVW];
__device__ float g_attn  [(size_t)BATCH * TSEQ * DMODEL];
__device__ float g_xr    [(size_t)BATCH * TSEQ * DMODEL];
__device__ float g_wqkv_t[(size_t)QKVW * DMODEL];
__device__ float g_wout_t[(size_t)DMODEL * DMODEL];

// ---------------------------------------------------------------------------
__device__ __forceinline__ uint32_t smem_u32(const void* p) {
    uint32_t a;
    asm("{ .reg .u64 t; cvta.to.shared.u64 t, %1; cvt.u32.u64 %0, t; }"
        : "=r"(a) : "l"(p));
    return a;
}
__device__ __forceinline__ float to_tf32(float x) {
    uint32_t u;
    asm("cvt.rna.tf32.f32 %0, %1;" : "=r"(u) : "f"(x));
    return __uint_as_float(u);
}
__device__ __forceinline__ void mma_m16n8k8_tf32(float* c, const uint32_t* a,
                                                 uint32_t b0, uint32_t b1) {
    asm volatile(
        "mma.sync.aligned.m16n8k8.row.col.f32.tf32.tf32.f32 "
        "{%0,%1,%2,%3}, {%4,%5,%6,%7}, {%8,%9}, {%0,%1,%2,%3};"
        : "+f"(c[0]), "+f"(c[1]), "+f"(c[2]), "+f"(c[3])
        : "r"(a[0]), "r"(a[1]), "r"(a[2]), "r"(a[3]), "r"(b0), "r"(b1));
}
__device__ __forceinline__ void ldsm_x4(uint32_t* r, uint32_t addr) {
    asm volatile("ldmatrix.sync.aligned.m8n8.x4.shared.b16 {%0,%1,%2,%3}, [%4];"
                 : "=r"(r[0]), "=r"(r[1]), "=r"(r[2]), "=r"(r[3]) : "r"(addr));
}

// ---------------------------------------------------------------------------
__global__ void transpose_rna(const float* __restrict__ W, float* __restrict__ Wt,
                              int K, int N)
{
    __shared__ float t[32][33];
    int n0 = blockIdx.x * 32, k0 = blockIdx.y * 32;
    int tx = threadIdx.x, ty = threadIdx.y;
#pragma unroll
    for (int r = 0; r < 32; r += 8)
        t[ty + r][tx] = W[(size_t)(k0 + ty + r) * N + n0 + tx];
    __syncthreads();
#pragma unroll
    for (int r = 0; r < 32; r += 8)
        Wt[(size_t)(n0 + ty + r) * K + k0 + tx] = to_tf32(t[tx][ty + r]);
}

__global__ void round_tf32_vec(const float* __restrict__ in, float* __restrict__ out,
                               int n4)
{
    int i = blockIdx.x * 256 + threadIdx.x;
    if (i >= n4) return;
    float4 v = ((const float4*)in)[i];
    v.x = to_tf32(v.x); v.y = to_tf32(v.y); v.z = to_tf32(v.z); v.w = to_tf32(v.w);
    ((float4*)out)[i] = v;
}

// ---------------------------------------------------------------------------
// mma.sync tf32 GEMM with ldmatrix fragment loads.
// C[M,N] = A[M,K] @ Bt[N,K]^T. 128x128 tile, BK=32, 8 warps (4x2),
// 3-stage cp.async, single barrier per mainloop iteration.
// ---------------------------------------------------------------------------
#define BK 32
#define AS_STRIDE 36
#define TILE_FLOATS (128 * AS_STRIDE)
#define TILE_BYTES  (TILE_FLOATS * 4)
#define GEMM_SMEM (6 * TILE_BYTES)        // 110592 B

__global__ __launch_bounds__(256, 2) void gemm_mma_tf32(
    const float* __restrict__ A, const float* __restrict__ Bt,
    float* __restrict__ C, int M, int N, int K)
{
    extern __shared__ float smf[];
    const uint32_t sm0 = smem_u32(smf);

    const int tid  = threadIdx.x;
    const int wid  = tid >> 5, lane = tid & 31;
    const int wm   = wid & 3, wn = wid >> 2;
    const int lr   = lane >> 2, lc = lane & 3;
    const int bm   = blockIdx.y * 128, bn = blockIdx.x * 128;
    const int NC   = K / BK;

    // ldmatrix per-thread byte offsets (within a stage buffer)
    const uint32_t aOff0 = ((uint32_t)((wm * 32 + (lane & 7) + ((lane >> 3) & 1) * 8)
                            * AS_STRIDE + (lane >> 4) * 4)) * 4;
    const uint32_t aOff1 = aOff0 + 16 * AS_STRIDE * 4;
    uint32_t bOff[4];
#pragma unroll
    for (int p = 0; p < 4; p++)
        bOff[p] = ((uint32_t)((wn * 64 + p * 16 + (lane & 7) + ((lane >> 4) & 1) * 8)
                   * AS_STRIDE + ((lane >> 3) & 1) * 4)) * 4;

    float acc[2][8][4];
#pragma unroll
    for (int i = 0; i < 2; i++)
#pragma unroll
        for (int j = 0; j < 8; j++)
#pragma unroll
            for (int q = 0; q < 4; q++) acc[i][j][q] = 0.f;

    auto load_stage = [&](int s, int k0) {
        uint32_t sA = sm0 + s * TILE_BYTES;
        uint32_t sB = sm0 + (3 + s) * TILE_BYTES;
#pragma unroll
        for (int it = 0; it < 4; it++) {
            int idx = it * 256 + tid;
            int row = idx >> 3, c4 = idx & 7;
            const float* g = A + (size_t)(bm + row) * K + k0 + c4 * 4;
            asm volatile("cp.async.cg.shared.global [%0], [%1], 16;"
                         :: "r"(sA + (uint32_t)(row * 144 + c4 * 16)), "l"(g));
        }
#pragma unroll
        for (int it = 0; it < 4; it++) {
            int idx = it * 256 + tid;
            int row = idx >> 3, c4 = idx & 7;
            const float* g = Bt + (size_t)(bn + row) * K + k0 + c4 * 4;
            asm volatile("cp.async.cg.shared.global [%0], [%1], 16;"
                         :: "r"(sB + (uint32_t)(row * 144 + c4 * 16)), "l"(g));
        }
        asm volatile("cp.async.commit_group;" ::: "memory");
    };

    load_stage(0, 0);
    load_stage(1, BK);

    int s = 0;
    for (int c = 0; c < NC; c++) {
        if (c + 1 < NC) {
            asm volatile("cp.async.wait_group 1;" ::: "memory");
        } else {
            asm volatile("cp.async.wait_group 0;" ::: "memory");
        }
        __syncthreads();
        if (c + 2 < NC) {
            int s2 = s + 2; if (s2 >= 3) s2 -= 3;
            load_stage(s2, (c + 2) * BK);
        }

        const uint32_t aBase = sm0 + s * TILE_BYTES;
        const uint32_t bBase = sm0 + (3 + s) * TILE_BYTES;
#pragma unroll
        for (int ks = 0; ks < 4; ks++) {
            uint32_t a0[4], a1[4], bb[16];
            ldsm_x4(a0, aBase + aOff0 + ks * 32);
            ldsm_x4(a1, aBase + aOff1 + ks * 32);
#pragma unroll
            for (int p = 0; p < 4; p++)
                ldsm_x4(&bb[4 * p], bBase + bOff[p] + ks * 32);
#pragma unroll
            for (int nt = 0; nt < 8; nt++) {
                mma_m16n8k8_tf32(acc[0][nt], a0, bb[2 * nt], bb[2 * nt + 1]);
                mma_m16n8k8_tf32(acc[1][nt], a1, bb[2 * nt], bb[2 * nt + 1]);
            }
        }
        s++; if (s == 3) s = 0;
    }

#pragma unroll
    for (int mt = 0; mt < 2; mt++) {
        int row = bm + wm * 32 + mt * 16 + lr;
#pragma unroll
        for (int nt = 0; nt < 8; nt++) {
            int col = bn + wn * 64 + nt * 8 + lc * 2;
            *(float2*)(C + (size_t)row * N + col) =
                make_float2(acc[mt][nt][0], acc[mt][nt][1]);
            *(float2*)(C + (size_t)(row + 8) * N + col) =
                make_float2(acc[mt][nt][2], acc[mt][nt][3]);
        }
    }
}

// ---------------------------------------------------------------------------
__global__ void rope_kernel(float* __restrict__ qkv,
                            const float* __restrict__ sinp,
                            const float* __restrict__ cosp)
{
    int idx = blockIdx.x * 256 + threadIdx.x;
    const int total = BATCH * TSEQ * (NHEADS + 1) * 64;
    if (idx >= total) return;
    int i = idx & 63;
    int rest = idx >> 6;
    int h = rest % (NHEADS + 1);
    int t = (rest / (NHEADS + 1)) % TSEQ;
    int b = rest / ((NHEADS + 1) * TSEQ);
    int col = (h < NHEADS) ? h * HDIM : DMODEL;
    float* base = qkv + ((size_t)(b * TSEQ + t)) * QKVW + col;
    float s = sinp[t * 64 + i];
    float c = cosp[t * 64 + i];
    float x1 = base[i];
    float x2 = base[64 + i];
    base[i]      = x1 * c - x2 * s;
    base[64 + i] = x2 * c + x1 * s;
}

// ---------------------------------------------------------------------------
// Flash attention via mma.sync tf32 + ldmatrix.
// ---------------------------------------------------------------------------
#define AST 132
#define ATT_SMEM_BYTES ((3 * 128 * AST + 260) * 4)

__global__ __launch_bounds__(256, 1) void attn_mma(
    const float* __restrict__ qkv, const int* __restrict__ doc,
    float* __restrict__ outa)
{
    extern __shared__ float smf[];
    float* Qs = smf;                       // [128][132]
    float* KVs = Qs + 128 * AST;           // K: [token][d]; later V^T: [d][token]
    float* Ps  = KVs + 128 * AST;          // [128][132]
    int* docq  = (int*)(Ps + 128 * AST);
    int* dock  = docq + 128;
    int* skst  = dock + 128;

    const int tid = threadIdx.x;
    const int wid = tid >> 5, lane = tid & 31;
    const int lr = lane >> 2, lc = lane & 3;
    const int qt = blockIdx.x, h = blockIdx.y, b = blockIdx.z;
    const int q0 = qt * 128;
    const float* qbase = qkv + (size_t)b * TSEQ * QKVW;
    const float SCALE = 0.08838834764831845f;

    const uint32_t QsB = smem_u32(Qs), KVB = smem_u32(KVs), PsB = smem_u32(Ps);
    // ldmatrix offsets
    const uint32_t qOff = ((uint32_t)((wid * 16 + (lane & 7) + ((lane >> 3) & 1) * 8)
                           * AST + (lane >> 4) * 4)) * 4;
    uint32_t kOff[8];
#pragma unroll
    for (int p = 0; p < 8; p++)
        kOff[p] = ((uint32_t)((p * 16 + (lane & 7) + ((lane >> 4) & 1) * 8)
                   * AST + ((lane >> 3) & 1) * 4)) * 4;

    // load Q tile, rounded
#pragma unroll
    for (int r = 0; r < 16; r++) {
        int li = r * 256 + tid;
        int row = li >> 5;
        int c4 = (li & 31) * 4;
        float4 v = *(const float4*)(qbase + (size_t)(q0 + row) * QKVW + h * HDIM + c4);
        v.x = to_tf32(v.x); v.y = to_tf32(v.y); v.z = to_tf32(v.z); v.w = to_tf32(v.w);
        *(float4*)&Qs[row * AST + c4] = v;
    }
    if (tid < 128) docq[tid] = doc[b * TSEQ + q0 + tid];
    if (tid == 0) {
        int d0 = doc[b * TSEQ + q0];
        int lo = 0, hi = q0;
        while (lo < hi) {
            int mid = (lo + hi) >> 1;
            if (doc[b * TSEQ + mid] < d0) lo = mid + 1; else hi = mid;
        }
        skst[0] = lo >> 7;
    }
    __syncthreads();

    const int kt_start = skst[0];
    const int r0g = q0 + wid * 16 + lr;
    const int r1g = r0g + 8;
    const int dq0 = docq[wid * 16 + lr];
    const int dq1 = docq[wid * 16 + lr + 8];

    float m0 = -1e30f, m1 = -1e30f, l0 = 0.f, l1 = 0.f;
    float O[16][4];
#pragma unroll
    for (int nt = 0; nt < 16; nt++)
#pragma unroll
        for (int q = 0; q < 4; q++) O[nt][q] = 0.f;

    for (int kt = kt_start; kt <= qt; kt++) {
        const int k0tok = kt * 128;
        const bool diag = (kt == qt);

        // load K tile [token][d], rounded
#pragma unroll
        for (int r = 0; r < 16; r++) {
            int li = r * 256 + tid;
            int row = li >> 5;
            int c4 = (li & 31) * 4;
            float4 v = *(const float4*)(qbase + (size_t)(k0tok + row) * QKVW + DMODEL + c4);
            v.x = to_tf32(v.x); v.y = to_tf32(v.y); v.z = to_tf32(v.z); v.w = to_tf32(v.w);
            *(float4*)&KVs[row * AST + c4] = v;
        }
        if (tid < 128) dock[tid] = doc[b * TSEQ + k0tok + tid];
        __syncthreads();

        // S = Q @ K^T
        float S[16][4];
#pragma unroll
        for (int nt = 0; nt < 16; nt++)
#pragma unroll
            for (int q = 0; q < 4; q++) S[nt][q] = 0.f;

#pragma unroll 4
        for (int k8 = 0; k8 < 16; k8++) {
            uint32_t qa[4];
            ldsm_x4(qa, QsB + qOff + k8 * 32);
#pragma unroll
            for (int p = 0; p < 8; p++) {
                uint32_t kb[4];
                ldsm_x4(kb, KVB + kOff[p] + k8 * 32);
                mma_m16n8k8_tf32(S[2 * p], qa, kb[0], kb[1]);
                mma_m16n8k8_tf32(S[2 * p + 1], qa, kb[2], kb[3]);
            }
        }

        // mask + online softmax
        float mx0 = -3.0e38f, mx1 = -3.0e38f;
#pragma unroll
        for (int nt = 0; nt < 16; nt++) {
            int cl = nt * 8 + 2 * lc;
            int2 dk = *(const int2*)&dock[cl];
            int gc0 = k0tok + cl, gc1 = gc0 + 1;
            bool ok00 = (dk.x == dq0) && (!diag || gc0 <= r0g);
            bool ok01 = (dk.y == dq0) && (!diag || gc1 <= r0g);
            bool ok10 = (dk.x == dq1) && (!diag || gc0 <= r1g);
            bool ok11 = (dk.y == dq1) && (!diag || gc1 <= r1g);
            S[nt][0] = ok00 ? S[nt][0] * SCALE : -1.7e38f;
            S[nt][1] = ok01 ? S[nt][1] * SCALE : -1.7e38f;
            S[nt][2] = ok10 ? S[nt][2] * SCALE : -1.7e38f;
            S[nt][3] = ok11 ? S[nt][3] * SCALE : -1.7e38f;
            mx0 = fmaxf(mx0, fmaxf(S[nt][0], S[nt][1]));
            mx1 = fmaxf(mx1, fmaxf(S[nt][2], S[nt][3]));
        }
        mx0 = fmaxf(mx0, __shfl_xor_sync(0xffffffffu, mx0, 1));
        mx0 = fmaxf(mx0, __shfl_xor_sync(0xffffffffu, mx0, 2));
        mx1 = fmaxf(mx1, __shfl_xor_sync(0xffffffffu, mx1, 1));
        mx1 = fmaxf(mx1, __shfl_xor_sync(0xffffffffu, mx1, 2));

        float mn0 = fmaxf(m0, mx0), mn1 = fmaxf(m1, mx1);
        float al0 = __expf(m0 - mn0), al1 = __expf(m1 - mn1);
        float sum0 = 0.f, sum1 = 0.f;
#pragma unroll
        for (int nt = 0; nt < 16; nt++) {
            float p00 = __expf(S[nt][0] - mn0);
            float p01 = __expf(S[nt][1] - mn0);
            float p10 = __expf(S[nt][2] - mn1);
            float p11 = __expf(S[nt][3] - mn1);
            sum0 += p00 + p01;
            sum1 += p10 + p11;
            int cl = nt * 8 + 2 * lc;
            *(float2*)&Ps[(wid * 16 + lr) * AST + cl] =
                make_float2(to_tf32(p00), to_tf32(p01));
            *(float2*)&Ps[(wid * 16 + lr + 8) * AST + cl] =
                make_float2(to_tf32(p10), to_tf32(p11));
        }
        sum0 += __shfl_xor_sync(0xffffffffu, sum0, 1);
        sum0 += __shfl_xor_sync(0xffffffffu, sum0, 2);
        sum1 += __shfl_xor_sync(0xffffffffu, sum1, 1);
        sum1 += __shfl_xor_sync(0xffffffffu, sum1, 2);
        l0 = l0 * al0 + sum0; m0 = mn0;
        l1 = l1 * al1 + sum1; m1 = mn1;
#pragma unroll
        for (int nt = 0; nt < 16; nt++) {
            O[nt][0] *= al0; O[nt][1] *= al0;
            O[nt][2] *= al1; O[nt][3] *= al1;
        }
        __syncthreads();

        // load V^T into KVs: Vt[d][token], rounded, rotated stores
#pragma unroll
        for (int r = 0; r < 16; r++) {
            int li = r * 256 + tid;
            int row = li >> 5;
            int lane4 = li & 31;
            int c4 = lane4 * 4;
            float4 v = *(const float4*)(qbase + (size_t)(k0tok + row) * QKVW + DMODEL + HDIM + c4);
            float vv[4] = {to_tf32(v.x), to_tf32(v.y), to_tf32(v.z), to_tf32(v.w)};
#pragma unroll
            for (int u = 0; u < 4; u++) {
                int uu = (u + lane4) & 3;
                KVs[(c4 + uu) * AST + row] = vv[uu];
            }
        }
        __syncthreads();

        // O += P @ V   (A = Ps rows via ldmatrix, B = Vt[d][token])
#pragma unroll 4
        for (int k8 = 0; k8 < 16; k8++) {
            uint32_t pa[4];
            ldsm_x4(pa, PsB + qOff + k8 * 32);
#pragma unroll
            for (int p = 0; p < 8; p++) {
                uint32_t vb[4];
                ldsm_x4(vb, KVB + kOff[p] + k8 * 32);
                mma_m16n8k8_tf32(O[2 * p], pa, vb[0], vb[1]);
                mma_m16n8k8_tf32(O[2 * p + 1], pa, vb[2], vb[3]);
            }
        }
        __syncthreads();
    }

    // epilogue
    float inv0 = 1.0f / l0, inv1 = 1.0f / l1;
    float* out0 = outa + (size_t)(b * TSEQ + r0g) * DMODEL + h * HDIM;
    float* out1 = outa + (size_t)(b * TSEQ + r1g) * DMODEL + h * HDIM;
#pragma unroll
    for (int nt = 0; nt < 16; nt++) {
        int cl = nt * 8 + 2 * lc;
        *(float2*)(out0 + cl) = make_float2(to_tf32(O[nt][0] * inv0),
                                            to_tf32(O[nt][1] * inv0));
        *(float2*)(out1 + cl) = make_float2(to_tf32(O[nt][2] * inv1),
                                            to_tf32(O[nt][3] * inv1));
    }
}

// ---------------------------------------------------------------------------
extern "C" void kernel_launch(void* const* d_in, const int* in_sizes, int n_in,
                              void* d_out, int out_size)
{
    const float* x    = (const float*)d_in[0];
    const float* sinp = (const float*)d_in[1];
    const float* cosp = (const float*)d_in[2];
    const int*   doc  = (const int*)d_in[3];
    const float* Wqkv = (const float*)d_in[4];
    const float* Wout = (const float*)d_in[5];
    float* out = (float*)d_out;

    float *qkv, *attn, *xr, *wqkv_t, *wout_t;
    cudaGetSymbolAddress((void**)&qkv,    g_qkv);
    cudaGetSymbolAddress((void**)&attn,   g_attn);
    cudaGetSymbolAddress((void**)&xr,     g_xr);
    cudaGetSymbolAddress((void**)&wqkv_t, g_wqkv_t);
    cudaGetSymbolAddress((void**)&wout_t, g_wout_t);

    cudaFuncSetAttribute(gemm_mma_tf32, cudaFuncAttributeMaxDynamicSharedMemorySize,
                         GEMM_SMEM);
    cudaFuncSetAttribute(attn_mma, cudaFuncAttributeMaxDynamicSharedMemorySize,
                         ATT_SMEM_BYTES);

    {
        dim3 bdim(32, 8);
        transpose_rna<<<dim3(QKVW / 32, DMODEL / 32), bdim>>>(Wqkv, wqkv_t, DMODEL, QKVW);
        transpose_rna<<<dim3(DMODEL / 32, DMODEL / 32), bdim>>>(Wout, wout_t, DMODEL, DMODEL);
        int n4 = MROWS * DMODEL / 4;
        round_tf32_vec<<<(n4 + 255) / 256, 256>>>(x, xr, n4);
    }

    {
        dim3 g(QKVW / 128, MROWS / 128);
        gemm_mma_tf32<<<g, 256, GEMM_SMEM>>>(xr, wqkv_t, qkv, MROWS, QKVW, DMODEL);
    }

    {
        int total = BATCH * TSEQ * (NHEADS + 1) * 64;
        rope_kernel<<<(total + 255) / 256, 256>>>(qkv, sinp, cosp);
    }

    {
        dim3 g(TSEQ / 128, NHEADS, BATCH);
        attn_mma<<<g, 256, ATT_SMEM_BYTES>>>(qkv, doc, attn);
    }

    {
        dim3 g(DMODEL / 128, MROWS / 128);
        gemm_mma_tf32<<<g, 256, GEMM_SMEM>>>(attn, wout_t, out, MROWS, DMODEL, DMODEL);
    }
}

// round 7
// speedup vs baseline: 3.5324x; 1.0729x over previous
#include <cuda_runtime.h>
#include <math.h>
#include <stdint.h>

#define TSEQ   2048
#define DMODEL 2048
#define NHEADS 16
#define HDIM   128
#define BATCH  2
#define QKVW   (DMODEL + 2*HDIM)   // 2304
#define MROWS  (BATCH*TSEQ)        // 4096

__device__ float g_qkv   [(size_t)BATCH * TSEQ * QKVW];
__device__ float g_attn  [(size_t)BATCH * TSEQ * DMODEL];
__device__ float g_xr    [(size_t)BATCH * TSEQ * DMODEL];
__device__ float g_wqkv_t[(size_t)QKVW * DMODEL];
__device__ float g_wout_t[(size_t)DMODEL * DMODEL];

// ---------------------------------------------------------------------------
__device__ __forceinline__ uint32_t smem_u32(const void* p) {
    uint32_t a;
    asm("{ .reg .u64 t; cvta.to.shared.u64 t, %1; cvt.u32.u64 %0, t; }"
        : "=r"(a) : "l"(p));
    return a;
}
__device__ __forceinline__ float to_tf32(float x) {
    uint32_t u;
    asm("cvt.rna.tf32.f32 %0, %1;" : "=r"(u) : "f"(x));
    return __uint_as_float(u);
}
__device__ __forceinline__ uint32_t to_tf32_bits(float x) {
    uint32_t u;
    asm("cvt.rna.tf32.f32 %0, %1;" : "=r"(u) : "f"(x));
    return u;
}
__device__ __forceinline__ void mma_m16n8k8_tf32(float* c, const uint32_t* a,
                                                 uint32_t b0, uint32_t b1) {
    asm volatile(
        "mma.sync.aligned.m16n8k8.row.col.f32.tf32.tf32.f32 "
        "{%0,%1,%2,%3}, {%4,%5,%6,%7}, {%8,%9}, {%0,%1,%2,%3};"
        : "+f"(c[0]), "+f"(c[1]), "+f"(c[2]), "+f"(c[3])
        : "r"(a[0]), "r"(a[1]), "r"(a[2]), "r"(a[3]), "r"(b0), "r"(b1));
}
__device__ __forceinline__ void ldsm_x4(uint32_t* r, uint32_t addr) {
    asm volatile("ldmatrix.sync.aligned.m8n8.x4.shared.b16 {%0,%1,%2,%3}, [%4];"
                 : "=r"(r[0]), "=r"(r[1]), "=r"(r[2]), "=r"(r[3]) : "r"(addr));
}

#define MBAR_INIT(a, n) \
    asm volatile("mbarrier.init.shared.b64 [%0], %1;" :: "r"(a), "r"(n) : "memory")
#define MBAR_ARRIVE(a) \
    asm volatile("mbarrier.arrive.shared.b64 _, [%0];" :: "r"(a) : "memory")
#define MBAR_WAIT(a, ph) do { \
    uint32_t _m = (a), _p = (ph), _d; \
    asm volatile("{ .reg .pred p; mbarrier.try_wait.parity.acquire.cta.shared::cta.b64 p, [%1], %2; selp.b32 %0,1,0,p; }" \
                 : "=r"(_d) : "r"(_m), "r"(_p) : "memory"); \
    if (!_d) { \
        asm volatile("{ .reg .pred P1; WL_%=: mbarrier.try_wait.parity.acquire.cta.shared::cta.b64 P1, [%0], %1, 0x989680; @P1 bra.uni WD_%=; bra.uni WL_%=; WD_%=: }" \
                     :: "r"(_m), "r"(_p) : "memory"); \
    } \
} while (0)
// .noinc is load-bearing: the expected count is pre-set at init (256); the
// non-noinc form increments-then-decrements (net 0) and the barrier never flips.
#define CPASYNC_MBAR_ARRIVE(a) \
    asm volatile("cp.async.mbarrier.arrive.noinc.shared.b64 [%0];" :: "r"(a) : "memory")

// ---------------------------------------------------------------------------
__global__ void transpose_rna(const float* __restrict__ W, float* __restrict__ Wt,
                              int K, int N)
{
    __shared__ float t[32][33];
    int n0 = blockIdx.x * 32, k0 = blockIdx.y * 32;
    int tx = threadIdx.x, ty = threadIdx.y;
#pragma unroll
    for (int r = 0; r < 32; r += 8)
        t[ty + r][tx] = W[(size_t)(k0 + ty + r) * N + n0 + tx];
    __syncthreads();
#pragma unroll
    for (int r = 0; r < 32; r += 8)
        Wt[(size_t)(n0 + ty + r) * K + k0 + tx] = to_tf32(t[tx][ty + r]);
}

__global__ void round_tf32_vec(const float* __restrict__ in, float* __restrict__ out,
                               int n4)
{
    int i = blockIdx.x * 256 + threadIdx.x;
    if (i >= n4) return;
    float4 v = ((const float4*)in)[i];
    v.x = to_tf32(v.x); v.y = to_tf32(v.y); v.z = to_tf32(v.z); v.w = to_tf32(v.w);
    ((float4*)out)[i] = v;
}

// ---------------------------------------------------------------------------
// mma.sync tf32 GEMM, mbarrier-pipelined (no mainloop __syncthreads).
// C[M,N] = A[M,K] @ Bt[N,K]^T. 128x128 tile, BK=32, 8 warps (4x2), 3 stages.
// ---------------------------------------------------------------------------
#define BK 32
#define AS_STRIDE 36
#define TILE_FLOATS (128 * AS_STRIDE)
#define TILE_BYTES  (TILE_FLOATS * 4)           // 18432
#define NSTAGE 3
#define GEMM_SMEM (2 * NSTAGE * TILE_BYTES + 64) // 110656

__global__ __launch_bounds__(256, 2) void gemm_mma_tf32(
    const float* __restrict__ A, const float* __restrict__ Bt,
    float* __restrict__ C, int M, int N, int K)
{
    extern __shared__ float smf[];
    const uint32_t sm0 = smem_u32(smf);
    const uint32_t mb0 = sm0 + 2 * NSTAGE * TILE_BYTES;   // full[0..2], empty[0..2]

    const int tid  = threadIdx.x;
    const int wid  = tid >> 5, lane = tid & 31;
    const int wm   = wid & 3, wn = wid >> 2;
    const int lr   = lane >> 2, lc = lane & 3;
    const int bm   = blockIdx.y * 128, bn = blockIdx.x * 128;
    const int NC   = K / BK;

    if (tid == 0) {
#pragma unroll
        for (int s = 0; s < NSTAGE; s++) {
            MBAR_INIT(mb0 + s * 8, 256);            // full
            MBAR_INIT(mb0 + 24 + s * 8, 8);         // empty
        }
    }
    __syncthreads();

    const uint32_t aOff0 = ((uint32_t)((wm * 32 + (lane & 7) + ((lane >> 3) & 1) * 8)
                            * AS_STRIDE + (lane >> 4) * 4)) * 4;
    const uint32_t aOff1 = aOff0 + 16 * AS_STRIDE * 4;
    uint32_t bOff[4];
#pragma unroll
    for (int p = 0; p < 4; p++)
        bOff[p] = ((uint32_t)((wn * 64 + p * 16 + (lane & 7) + ((lane >> 4) & 1) * 8)
                   * AS_STRIDE + ((lane >> 3) & 1) * 4)) * 4;

    float acc[2][8][4];
#pragma unroll
    for (int i = 0; i < 2; i++)
#pragma unroll
        for (int j = 0; j < 8; j++)
#pragma unroll
            for (int q = 0; q < 4; q++) acc[i][j][q] = 0.f;

    const int ldrow = tid >> 3, ldc4 = tid & 7;
    auto produce = [&](int s, int k0) {
        uint32_t sA = sm0 + s * TILE_BYTES;
        uint32_t sB = sm0 + (NSTAGE + s) * TILE_BYTES;
#pragma unroll
        for (int it = 0; it < 4; it++) {
            int row = it * 32 + ldrow;
            const float* g = A + (size_t)(bm + row) * K + k0 + ldc4 * 4;
            asm volatile("cp.async.cg.shared.global [%0], [%1], 16;"
                         :: "r"(sA + (uint32_t)(row * 144 + ldc4 * 16)), "l"(g));
        }
#pragma unroll
        for (int it = 0; it < 4; it++) {
            int row = it * 32 + ldrow;
            const float* g = Bt + (size_t)(bn + row) * K + k0 + ldc4 * 4;
            asm volatile("cp.async.cg.shared.global [%0], [%1], 16;"
                         :: "r"(sB + (uint32_t)(row * 144 + ldc4 * 16)), "l"(g));
        }
        CPASYNC_MBAR_ARRIVE(mb0 + s * 8);
    };

    // prologue: fill all 3 stages
    produce(0, 0);
    produce(1, BK);
    produce(2, 2 * BK);

    int s = 0, ph = 0;
    for (int c = 0; c < NC; c++) {
        MBAR_WAIT(mb0 + s * 8, (uint32_t)ph);

        const uint32_t aBase = sm0 + s * TILE_BYTES;
        const uint32_t bBase = sm0 + (NSTAGE + s) * TILE_BYTES;
#pragma unroll
        for (int ks = 0; ks < 4; ks++) {
            uint32_t a0[4], a1[4], bb[16];
            ldsm_x4(a0, aBase + aOff0 + ks * 32);
            ldsm_x4(a1, aBase + aOff1 + ks * 32);
#pragma unroll
            for (int p = 0; p < 4; p++)
                ldsm_x4(&bb[4 * p], bBase + bOff[p] + ks * 32);
#pragma unroll
            for (int nt = 0; nt < 8; nt++) {
                mma_m16n8k8_tf32(acc[0][nt], a0, bb[2 * nt], bb[2 * nt + 1]);
                mma_m16n8k8_tf32(acc[1][nt], a1, bb[2 * nt], bb[2 * nt + 1]);
            }
        }
        if (lane == 0) MBAR_ARRIVE(mb0 + 24 + s * 8);

        if (c + NSTAGE < NC) {
            MBAR_WAIT(mb0 + 24 + s * 8, (uint32_t)ph);
            produce(s, (c + NSTAGE) * BK);
        }
        s++; if (s == NSTAGE) { s = 0; ph ^= 1; }
    }

#pragma unroll
    for (int mt = 0; mt < 2; mt++) {
        int row = bm + wm * 32 + mt * 16 + lr;
#pragma unroll
        for (int nt = 0; nt < 8; nt++) {
            int col = bn + wn * 64 + nt * 8 + lc * 2;
            *(float2*)(C + (size_t)row * N + col) =
                make_float2(acc[mt][nt][0], acc[mt][nt][1]);
            *(float2*)(C + (size_t)(row + 8) * N + col) =
                make_float2(acc[mt][nt][2], acc[mt][nt][3]);
        }
    }
}

// ---------------------------------------------------------------------------
__global__ void rope_kernel(float* __restrict__ qkv,
                            const float* __restrict__ sinp,
                            const float* __restrict__ cosp)
{
    int idx = blockIdx.x * 256 + threadIdx.x;
    const int total = BATCH * TSEQ * (NHEADS + 1) * 64;
    if (idx >= total) return;
    int i = idx & 63;
    int rest = idx >> 6;
    int h = rest % (NHEADS + 1);
    int t = (rest / (NHEADS + 1)) % TSEQ;
    int b = rest / ((NHEADS + 1) * TSEQ);
    int col = (h < NHEADS) ? h * HDIM : DMODEL;
    float* base = qkv + ((size_t)(b * TSEQ + t)) * QKVW + col;
    float s = sinp[t * 64 + i];
    float c = cosp[t * 64 + i];
    float x1 = base[i];
    float x2 = base[64 + i];
    base[i]      = x1 * c - x2 * s;
    base[64 + i] = x2 * c + x1 * s;
}

// ---------------------------------------------------------------------------
// Flash attention, mma.sync tf32 + ldmatrix.
// V prefetched via cp.async; P relayout accumulator->A-frag via shuffles.
// ---------------------------------------------------------------------------
#define AST 132
#define ATT_Q_OFF   0
#define ATT_KV_OFF  (128 * AST)
#define ATT_VR_OFF  (2 * 128 * AST)
#define ATT_DOC_OFF (2 * 128 * AST + 128 * 128)
#define ATT_SMEM_BYTES ((ATT_DOC_OFF + 260) * 4)

__global__ __launch_bounds__(256, 1) void attn_mma(
    const float* __restrict__ qkv, const int* __restrict__ doc,
    float* __restrict__ outa)
{
    extern __shared__ float smf[];
    float* Qs   = smf + ATT_Q_OFF;
    float* KVt  = smf + ATT_KV_OFF;
    float* Vrow = smf + ATT_VR_OFF;
    int* docq   = (int*)(smf + ATT_DOC_OFF);
    int* dock   = docq + 128;
    int* skst   = dock + 128;

    const int tid = threadIdx.x;
    const int wid = tid >> 5, lane = tid & 31;
    const int lr = lane >> 2, lc = lane & 3;
    const int qt = blockIdx.x, h = blockIdx.y, b = blockIdx.z;
    const int q0 = qt * 128;
    const float* qbase = qkv + (size_t)b * TSEQ * QKVW;
    const float SCALE = 0.08838834764831845f;

    const uint32_t QsB = smem_u32(Qs), KVB = smem_u32(KVt), VRB = smem_u32(Vrow);
    const uint32_t qOff = ((uint32_t)((wid * 16 + (lane & 7) + ((lane >> 3) & 1) * 8)
                           * AST + (lane >> 4) * 4)) * 4;
    uint32_t kOff[8];
#pragma unroll
    for (int p = 0; p < 8; p++)
        kOff[p] = ((uint32_t)((p * 16 + (lane & 7) + ((lane >> 4) & 1) * 8)
                   * AST + ((lane >> 3) & 1) * 4)) * 4;

    const int sl1 = lr * 4 + (lc >> 1);
    const int sl2 = sl1 + 2;
    const bool odd = (lc & 1);

#pragma unroll
    for (int r = 0; r < 16; r++) {
        int li = r * 256 + tid;
        int row = li >> 5;
        int c4 = (li & 31) * 4;
        float4 v = *(const float4*)(qbase + (size_t)(q0 + row) * QKVW + h * HDIM + c4);
        v.x = to_tf32(v.x); v.y = to_tf32(v.y); v.z = to_tf32(v.z); v.w = to_tf32(v.w);
        *(float4*)&Qs[row * AST + c4] = v;
    }
    if (tid < 128) docq[tid] = doc[b * TSEQ + q0 + tid];
    if (tid == 0) {
        int d0 = doc[b * TSEQ + q0];
        int lo = 0, hi = q0;
        while (lo < hi) {
            int mid = (lo + hi) >> 1;
            if (doc[b * TSEQ + mid] < d0) lo = mid + 1; else hi = mid;
        }
        skst[0] = lo >> 7;
    }
    __syncthreads();

    const int kt_start = skst[0];
    const int r0g = q0 + wid * 16 + lr;
    const int r1g = r0g + 8;
    const int dq0 = docq[wid * 16 + lr];
    const int dq1 = docq[wid * 16 + lr + 8];

    float m0 = -1e30f, m1 = -1e30f, l0 = 0.f, l1 = 0.f;
    float O[16][4];
#pragma unroll
    for (int nt = 0; nt < 16; nt++)
#pragma unroll
        for (int q = 0; q < 4; q++) O[nt][q] = 0.f;

    for (int kt = kt_start; kt <= qt; kt++) {
        const int k0tok = kt * 128;
        const bool diag = (kt == qt);

        // prefetch V tile (raw fp32) into Vrow via cp.async
#pragma unroll
        for (int r = 0; r < 16; r++) {
            int li = r * 256 + tid;
            int row = li >> 5;
            int c4 = (li & 31) * 4;
            const float* g = qbase + (size_t)(k0tok + row) * QKVW + DMODEL + HDIM + c4;
            asm volatile("cp.async.cg.shared.global [%0], [%1], 16;"
                         :: "r"(VRB + (uint32_t)((row * 128 + c4) * 4)), "l"(g));
        }
        asm volatile("cp.async.commit_group;" ::: "memory");

        // load K tile [token][d], rounded
#pragma unroll
        for (int r = 0; r < 16; r++) {
            int li = r * 256 + tid;
            int row = li >> 5;
            int c4 = (li & 31) * 4;
            float4 v = *(const float4*)(qbase + (size_t)(k0tok + row) * QKVW + DMODEL + c4);
            v.x = to_tf32(v.x); v.y = to_tf32(v.y); v.z = to_tf32(v.z); v.w = to_tf32(v.w);
            *(float4*)&KVt[row * AST + c4] = v;
        }
        if (tid < 128) dock[tid] = doc[b * TSEQ + k0tok + tid];
        __syncthreads();

        // S = Q @ K^T
        float S[16][4];
#pragma unroll
        for (int nt = 0; nt < 16; nt++)
#pragma unroll
            for (int q = 0; q < 4; q++) S[nt][q] = 0.f;

#pragma unroll 4
        for (int k8 = 0; k8 < 16; k8++) {
            uint32_t qa[4];
            ldsm_x4(qa, QsB + qOff + k8 * 32);
#pragma unroll
            for (int p = 0; p < 8; p++) {
                uint32_t kb[4];
                ldsm_x4(kb, KVB + kOff[p] + k8 * 32);
                mma_m16n8k8_tf32(S[2 * p], qa, kb[0], kb[1]);
                mma_m16n8k8_tf32(S[2 * p + 1], qa, kb[2], kb[3]);
            }
        }

        // mask + online softmax -> Pr (tf32 bits, accumulator layout)
        uint32_t Pr[16][4];
        float mx0 = -3.0e38f, mx1 = -3.0e38f;
#pragma unroll
        for (int nt = 0; nt < 16; nt++) {
            int cl = nt * 8 + 2 * lc;
            int2 dk = *(const int2*)&dock[cl];
            int gc0 = k0tok + cl, gc1 = gc0 + 1;
            bool ok00 = (dk.x == dq0) && (!diag || gc0 <= r0g);
            bool ok01 = (dk.y == dq0) && (!diag || gc1 <= r0g);
            bool ok10 = (dk.x == dq1) && (!diag || gc0 <= r1g);
            bool ok11 = (dk.y == dq1) && (!diag || gc1 <= r1g);
            S[nt][0] = ok00 ? S[nt][0] * SCALE : -1.7e38f;
            S[nt][1] = ok01 ? S[nt][1] * SCALE : -1.7e38f;
            S[nt][2] = ok10 ? S[nt][2] * SCALE : -1.7e38f;
            S[nt][3] = ok11 ? S[nt][3] * SCALE : -1.7e38f;
            mx0 = fmaxf(mx0, fmaxf(S[nt][0], S[nt][1]));
            mx1 = fmaxf(mx1, fmaxf(S[nt][2], S[nt][3]));
        }
        mx0 = fmaxf(mx0, __shfl_xor_sync(0xffffffffu, mx0, 1));
        mx0 = fmaxf(mx0, __shfl_xor_sync(0xffffffffu, mx0, 2));
        mx1 = fmaxf(mx1, __shfl_xor_sync(0xffffffffu, mx1, 1));
        mx1 = fmaxf(mx1, __shfl_xor_sync(0xffffffffu, mx1, 2));

        float mn0 = fmaxf(m0, mx0), mn1 = fmaxf(m1, mx1);
        float al0 = __expf(m0 - mn0), al1 = __expf(m1 - mn1);
        float sum0 = 0.f, sum1 = 0.f;
#pragma unroll
        for (int nt = 0; nt < 16; nt++) {
            float p00 = __expf(S[nt][0] - mn0);
            float p01 = __expf(S[nt][1] - mn0);
            float p10 = __expf(S[nt][2] - mn1);
            float p11 = __expf(S[nt][3] - mn1);
            sum0 += p00 + p01;
            sum1 += p10 + p11;
            Pr[nt][0] = to_tf32_bits(p00);
            Pr[nt][1] = to_tf32_bits(p01);
            Pr[nt][2] = to_tf32_bits(p10);
            Pr[nt][3] = to_tf32_bits(p11);
        }
        sum0 += __shfl_xor_sync(0xffffffffu, sum0, 1);
        sum0 += __shfl_xor_sync(0xffffffffu, sum0, 2);
        sum1 += __shfl_xor_sync(0xffffffffu, sum1, 1);
        sum1 += __shfl_xor_sync(0xffffffffu, sum1, 2);
        l0 = l0 * al0 + sum0; m0 = mn0;
        l1 = l1 * al1 + sum1; m1 = mn1;
#pragma unroll
        for (int nt = 0; nt < 16; nt++) {
            O[nt][0] *= al0; O[nt][1] *= al0;
            O[nt][2] *= al1; O[nt][3] *= al1;
        }

        asm volatile("cp.async.wait_group 0;" ::: "memory");
        __syncthreads();

        // transpose V: Vrow[token][d] -> KVt[d][token], rounded, rotated stores
#pragma unroll
        for (int r = 0; r < 16; r++) {
            int li = r * 256 + tid;
            int row = li >> 5;
            int lane4 = li & 31;
            int c4 = lane4 * 4;
            float4 v = *(const float4*)&Vrow[row * 128 + c4];
            float vv[4] = {to_tf32(v.x), to_tf32(v.y), to_tf32(v.z), to_tf32(v.w)};
#pragma unroll
            for (int u = 0; u < 4; u++) {
                int uu = (u + lane4) & 3;
                KVt[(c4 + uu) * AST + row] = vv[uu];
            }
        }
        __syncthreads();

        // O += P @ V
#pragma unroll 4
        for (int k8 = 0; k8 < 16; k8++) {
            uint32_t pa[4];
            {
                uint32_t u0 = __shfl_sync(0xffffffffu, Pr[k8][0], sl1);
                uint32_t u1 = __shfl_sync(0xffffffffu, Pr[k8][1], sl1);
                uint32_t u2 = __shfl_sync(0xffffffffu, Pr[k8][2], sl1);
                uint32_t u3 = __shfl_sync(0xffffffffu, Pr[k8][3], sl1);
                uint32_t v0 = __shfl_sync(0xffffffffu, Pr[k8][0], sl2);
                uint32_t v1 = __shfl_sync(0xffffffffu, Pr[k8][1], sl2);
                uint32_t v2 = __shfl_sync(0xffffffffu, Pr[k8][2], sl2);
                uint32_t v3 = __shfl_sync(0xffffffffu, Pr[k8][3], sl2);
                pa[0] = odd ? u1 : u0;
                pa[1] = odd ? u3 : u2;
                pa[2] = odd ? v1 : v0;
                pa[3] = odd ? v3 : v2;
            }
#pragma unroll
            for (int p = 0; p < 8; p++) {
                uint32_t vb[4];
                ldsm_x4(vb, KVB + kOff[p] + k8 * 32);
                mma_m16n8k8_tf32(O[2 * p], pa, vb[0], vb[1]);
                mma_m16n8k8_tf32(O[2 * p + 1], pa, vb[2], vb[3]);
            }
        }
        __syncthreads();
    }

    // epilogue
    float inv0 = 1.0f / l0, inv1 = 1.0f / l1;
    float* out0 = outa + (size_t)(b * TSEQ + r0g) * DMODEL + h * HDIM;
    float* out1 = outa + (size_t)(b * TSEQ + r1g) * DMODEL + h * HDIM;
#pragma unroll
    for (int nt = 0; nt < 16; nt++) {
        int cl = nt * 8 + 2 * lc;
        *(float2*)(out0 + cl) = make_float2(to_tf32(O[nt][0] * inv0),
                                            to_tf32(O[nt][1] * inv0));
        *(float2*)(out1 + cl) = make_float2(to_tf32(O[nt][2] * inv1),
                                            to_tf32(O[nt][3] * inv1));
    }
}

// ---------------------------------------------------------------------------
extern "C" void kernel_launch(void* const* d_in, const int* in_sizes, int n_in,
                              void* d_out, int out_size)
{
    const float* x    = (const float*)d_in[0];
    const float* sinp = (const float*)d_in[1];
    const float* cosp = (const float*)d_in[2];
    const int*   doc  = (const int*)d_in[3];
    const float* Wqkv = (const float*)d_in[4];
    const float* Wout = (const float*)d_in[5];
    float* out = (float*)d_out;

    float *qkv, *attn, *xr, *wqkv_t, *wout_t;
    cudaGetSymbolAddress((void**)&qkv,    g_qkv);
    cudaGetSymbolAddress((void**)&attn,   g_attn);
    cudaGetSymbolAddress((void**)&xr,     g_xr);
    cudaGetSymbolAddress((void**)&wqkv_t, g_wqkv_t);
    cudaGetSymbolAddress((void**)&wout_t, g_wout_t);

    cudaFuncSetAttribute(gemm_mma_tf32, cudaFuncAttributeMaxDynamicSharedMemorySize,
                         GEMM_SMEM);
    cudaFuncSetAttribute(attn_mma, cudaFuncAttributeMaxDynamicSharedMemorySize,
                         ATT_SMEM_BYTES);

    {
        dim3 bdim(32, 8);
        transpose_rna<<<dim3(QKVW / 32, DMODEL / 32), bdim>>>(Wqkv, wqkv_t, DMODEL, QKVW);
        transpose_rna<<<dim3(DMODEL / 32, DMODEL / 32), bdim>>>(Wout, wout_t, DMODEL, DMODEL);
        int n4 = MROWS * DMODEL / 4;
        round_tf32_vec<<<(n4 + 255) / 256, 256>>>(x, xr, n4);
    }

    {
        dim3 g(QKVW / 128, MROWS / 128);
        gemm_mma_tf32<<<g, 256, GEMM_SMEM>>>(xr, wqkv_t, qkv, MROWS, QKVW, DMODEL);
    }

    {
        int total = BATCH * TSEQ * (NHEADS + 1) * 64;
        rope_kernel<<<(total + 255) / 256, 256>>>(qkv, sinp, cosp);
    }

    {
        dim3 g(TSEQ / 128, NHEADS, BATCH);
        attn_mma<<<g, 256, ATT_SMEM_BYTES>>>(qkv, doc, attn);
    }

    {
        dim3 g(DMODEL / 128, MROWS / 128);
        gemm_mma_tf32<<<g, 256, GEMM_SMEM>>>(attn, wout_t, out, MROWS, DMODEL, DMODEL);
    }
}